// round 10
// baseline (speedup 1.0000x reference)
#include <cuda_runtime.h>
#include <cstdint>

// ---------------------------------------------------------------------------
// MultiHeadAttention B=2,S=2048,D=1024,H=16,Dh=64 fp32 — R10:
//  * GEMMs: R6 config (4 warps, 64x64/warp, As[128][36]/Bs[32][136], 2 blk/SM)
//  * Attention: R9 ldmatrix layouts, widened to 16 warps (512 thr, m16n64)
// ---------------------------------------------------------------------------

constexpr int BB = 2;
constexpr int SS = 2048;
constexpr int DD = 1024;
constexpr int HH = 16;
constexpr int DH = 64;
constexpr int MT = BB * SS;   // 4096

__device__ float g_q[BB * HH * SS * DH];
__device__ float g_k[BB * HH * SS * DH];
__device__ float g_vt[BB * HH * DH * SS];   // V transposed: [b,h,dh,s]
__device__ float g_att[MT * DD];
__device__ float g_xt[MT * DD];
__device__ float g_wqt[DD * DD];
__device__ float g_wkt[DD * DD];
__device__ float g_wvt[DD * DD];
__device__ float g_wot[DD * DD];

__device__ __forceinline__ uint32_t f2tf(float x) {
    uint32_t r;
    asm("cvt.rna.tf32.f32 %0, %1;" : "=r"(r) : "f"(x));
    return r;
}
__device__ __forceinline__ void mma8(float* d, uint32_t a0, uint32_t a1,
                                     uint32_t a2, uint32_t a3,
                                     uint32_t b0, uint32_t b1) {
    asm volatile(
        "mma.sync.aligned.m16n8k8.row.col.f32.tf32.tf32.f32 "
        "{%0,%1,%2,%3}, {%4,%5,%6,%7}, {%8,%9}, {%0,%1,%2,%3};"
        : "+f"(d[0]), "+f"(d[1]), "+f"(d[2]), "+f"(d[3])
        : "r"(a0), "r"(a1), "r"(a2), "r"(a3), "r"(b0), "r"(b1));
}
__device__ __forceinline__ void ldsm4(uint32_t& r0, uint32_t& r1,
                                      uint32_t& r2, uint32_t& r3,
                                      uint32_t addr) {
    asm volatile(
        "ldmatrix.sync.aligned.m8n8.x4.shared.b16 {%0,%1,%2,%3}, [%4];"
        : "=r"(r0), "=r"(r1), "=r"(r2), "=r"(r3) : "r"(addr));
}
__device__ __forceinline__ void cp16(uint32_t dst, const void* src) {
    asm volatile("cp.async.cg.shared.global [%0], [%1], 16;"
                 :: "r"(dst), "l"(src));
}
__device__ __forceinline__ void cp_commit() {
    asm volatile("cp.async.commit_group;");
}
template <int N>
__device__ __forceinline__ void cp_wait() {
    asm volatile("cp.async.wait_group %0;" :: "n"(N));
}
__device__ __forceinline__ float4 cvt4(float4 v) {
    float4 o;
    o.x = __uint_as_float(f2tf(v.x));
    o.y = __uint_as_float(f2tf(v.y));
    o.z = __uint_as_float(f2tf(v.z));
    o.w = __uint_as_float(f2tf(v.w));
    return o;
}

// ---------------------------------------------------------------------------
// K0: pre-round x, wq, wk, wv, wo.
// ---------------------------------------------------------------------------
__global__ __launch_bounds__(256) void cvt_inputs(
    const float* __restrict__ x,
    const float* __restrict__ wq, const float* __restrict__ wk,
    const float* __restrict__ wv, const float* __restrict__ wo)
{
    const int z = blockIdx.y;
    const float* src = (z == 0) ? x : (z == 1) ? wq : (z == 2) ? wk
                       : (z == 3) ? wv : wo;
    float* dst = (z == 0) ? g_xt : (z == 1) ? g_wqt : (z == 2) ? g_wkt
                 : (z == 3) ? g_wvt : g_wot;
    const int n4 = ((z == 0) ? MT * DD : DD * DD) >> 2;
    const float4* s4 = reinterpret_cast<const float4*>(src);
    float4* d4 = reinterpret_cast<float4*>(dst);
    for (int i = blockIdx.x * blockDim.x + threadIdx.x; i < n4;
         i += gridDim.x * blockDim.x)
        d4[i] = cvt4(s4[i]);
}

// ---------------------------------------------------------------------------
// GEMM (R6): 128x128 tile, BK=32, 4 warps (2x2), 64x64/warp, 3-stage cp.async.
// ---------------------------------------------------------------------------
constexpr int AS_ELEM = 128 * 36;
constexpr int BS_ELEM = 32 * 136;
constexpr int GEMM_SMEM = 3 * (AS_ELEM + BS_ELEM) * (int)sizeof(float);

__device__ __forceinline__ void gemm_stage(
    uint32_t As_s, uint32_t Bs_s, int s, const float* __restrict__ A,
    const float* __restrict__ B, int brow, int bcol, int kk, int tid)
{
#pragma unroll
    for (int i = 0; i < 8; i++) {
        int idx = tid + (i << 7);
        int r = idx >> 3, c4 = (idx & 7) << 2;
        cp16(As_s + (s * AS_ELEM + r * 36 + c4) * 4,
             A + (size_t)(brow + r) * DD + kk + c4);
    }
#pragma unroll
    for (int i = 0; i < 8; i++) {
        int idx = tid + (i << 7);
        int r = idx >> 5, c4 = (idx & 31) << 2;
        cp16(Bs_s + (s * BS_ELEM + r * 136 + c4) * 4,
             B + (size_t)(kk + r) * DD + bcol + c4);
    }
    cp_commit();
}

__device__ __forceinline__ void gemm_compute(
    const float* As, const float* Bs, int lane, int wm, int wn,
    float acc[4][8][4])
{
    const int ar = wm * 64 + (lane >> 2);
    const int bc = wn * 64 + (lane >> 2);
#pragma unroll
    for (int ks = 0; ks < 4; ks++) {
        const int k0 = ks * 8;
        uint32_t a[4][4], b[8][2];
        const int acl = k0 + (lane & 3);
#pragma unroll
        for (int mi = 0; mi < 4; mi++) {
            const float* p = &As[(ar + mi * 16) * 36 + acl];
            a[mi][0] = __float_as_uint(p[0]);
            a[mi][2] = __float_as_uint(p[4]);
            a[mi][1] = __float_as_uint(p[8 * 36]);
            a[mi][3] = __float_as_uint(p[8 * 36 + 4]);
        }
        const int br = k0 + (lane & 3);
#pragma unroll
        for (int ni = 0; ni < 8; ni++) {
            const float* p = &Bs[br * 136 + bc + ni * 8];
            b[ni][0] = __float_as_uint(p[0]);
            b[ni][1] = __float_as_uint(p[4 * 136]);
        }
#pragma unroll
        for (int mi = 0; mi < 4; mi++)
#pragma unroll
            for (int ni = 0; ni < 8; ni++)
                mma8(acc[mi][ni], a[mi][0], a[mi][1], a[mi][2], a[mi][3],
                     b[ni][0], b[ni][1]);
    }
}

template <typename EpiF>
__device__ __forceinline__ void gemm_run(
    float* sm, const float* __restrict__ A, const float* __restrict__ B,
    int brow, int bcol, EpiF epi)
{
    const uint32_t As_s = (uint32_t)__cvta_generic_to_shared(sm);
    const uint32_t Bs_s = (uint32_t)__cvta_generic_to_shared(sm + 3 * AS_ELEM);
    const float* AsB = sm;
    const float* BsB = sm + 3 * AS_ELEM;

    const int tid = threadIdx.x;
    const int lane = tid & 31;
    const int warp = tid >> 5;
    const int wm = warp >> 1, wn = warp & 1;

    float acc[4][8][4];
#pragma unroll
    for (int mi = 0; mi < 4; mi++)
#pragma unroll
        for (int ni = 0; ni < 8; ni++)
#pragma unroll
            for (int f = 0; f < 4; f++) acc[mi][ni][f] = 0.f;

    constexpr int NCH = DD / 32;
    gemm_stage(As_s, Bs_s, 0, A, B, brow, bcol, 0, tid);
    gemm_stage(As_s, Bs_s, 1, A, B, brow, bcol, 32, tid);

    for (int i = 0; i < NCH; i++) {
        if (i + 1 < NCH) cp_wait<1>(); else cp_wait<0>();
        __syncthreads();
        if (i + 2 < NCH)
            gemm_stage(As_s, Bs_s, (i + 2) % 3, A, B, brow, bcol,
                       (i + 2) * 32, tid);
        gemm_compute(AsB + (i % 3) * AS_ELEM, BsB + (i % 3) * BS_ELEM,
                     lane, wm, wn, acc);
    }
    epi(acc, lane, wm, wn);
}

// ---------------------------------------------------------------------------
// K1: QKV GEMM + RoPE.  mat==2 (V): smem transpose -> g_vt[b,h,dh,s].
// ---------------------------------------------------------------------------
__global__ __launch_bounds__(128, 2) void qkv_mma(
    const float* __restrict__ cosT, const float* __restrict__ sinT)
{
    extern __shared__ float sm[];
    const int mat = blockIdx.z;
    const float* __restrict__ w =
        (mat == 0) ? g_wqt : (mat == 1) ? g_wkt : g_wvt;
    const int brow = blockIdx.y * 128;
    const int bcol = blockIdx.x * 128;

    gemm_run(sm, g_xt, w, brow, bcol,
        [&](float acc[4][8][4], int lane, int wm, int wn) {
            const int tid = threadIdx.x;
            if (mat < 2) {
                float* __restrict__ out = (mat == 0) ? g_q : g_k;
                const int ar = wm * 64 + (lane >> 2);
                const int ac = wn * 64 + (lane & 3) * 2;
#pragma unroll
                for (int mi = 0; mi < 4; mi++) {
#pragma unroll
                    for (int hp = 0; hp < 2; hp++) {
                        const int row = brow + ar + mi * 16 + hp * 8;
                        const int bb = row >> 11;
                        const int ss = row & (SS - 1);
#pragma unroll
                        for (int ni = 0; ni < 8; ni++) {
                            const int col = bcol + ac + ni * 8;
                            const int hh = col >> 6;
                            const int dh = col & (DH - 1);
                            float c0 = acc[mi][ni][hp * 2 + 0];
                            float c1 = acc[mi][ni][hp * 2 + 1];
                            const int fi = ss * 32 + (dh >> 1);
                            const float cs = cosT[fi], sn = sinT[fi];
                            const float o0 = c0 * cs - c1 * sn;
                            const float o1 = c0 * sn + c1 * cs;
                            c0 = o0; c1 = o1;
                            if (mat == 0) { c0 *= 0.125f; c1 *= 0.125f; }
                            *reinterpret_cast<float2*>(
                                out + ((size_t)(bb * HH + hh) * SS + ss) * DH + dh) =
                                make_float2(__uint_as_float(f2tf(c0)),
                                            __uint_as_float(f2tf(c1)));
                        }
                    }
                }
            } else {
                __syncthreads();
                float* T = sm;
                const int ar = wm * 64 + (lane >> 2);
                const int ac = wn * 64 + (lane & 3) * 2;
#pragma unroll
                for (int mi = 0; mi < 4; mi++)
#pragma unroll
                    for (int hp = 0; hp < 2; hp++) {
                        const int rl = ar + mi * 16 + hp * 8;
#pragma unroll
                        for (int ni = 0; ni < 8; ni++) {
                            const int cl = ac + ni * 8;
                            T[(cl)     * 132 + rl] =
                                __uint_as_float(f2tf(acc[mi][ni][hp * 2]));
                            T[(cl + 1) * 132 + rl] =
                                __uint_as_float(f2tf(acc[mi][ni][hp * 2 + 1]));
                        }
                    }
                __syncthreads();
                const int bb = brow >> 11;
                const int srow = brow & (SS - 1);
#pragma unroll
                for (int i = 0; i < 32; i++) {
                    int idx = tid + (i << 7);
                    int r = idx >> 5, c4 = (idx & 31) << 2;
                    const int dhg = bcol + r;
                    const int hh = dhg >> 6, dh = dhg & 63;
                    float4 v = *reinterpret_cast<float4*>(&T[r * 132 + c4]);
                    *reinterpret_cast<float4*>(
                        g_vt + ((size_t)(bb * HH + hh) * DH + dh) * SS +
                        srow + c4) = v;
                }
            }
        });
}

// ---------------------------------------------------------------------------
// K3: output projection (R6)
// ---------------------------------------------------------------------------
__global__ __launch_bounds__(128, 2) void proj_mma(float* __restrict__ Cout)
{
    extern __shared__ float sm[];
    const int brow = blockIdx.y * 128;
    const int bcol = blockIdx.x * 128;

    gemm_run(sm, g_att, g_wot, brow, bcol,
        [&](float acc[4][8][4], int lane, int wm, int wn) {
            const int ar = wm * 64 + (lane >> 2);
            const int ac = wn * 64 + (lane & 3) * 2;
#pragma unroll
            for (int mi = 0; mi < 4; mi++)
#pragma unroll
                for (int hp = 0; hp < 2; hp++) {
                    const int row = brow + ar + mi * 16 + hp * 8;
#pragma unroll
                    for (int ni = 0; ni < 8; ni++) {
                        const int col = bcol + ac + ni * 8;
                        *reinterpret_cast<float2*>(
                            Cout + (size_t)row * DD + col) =
                            make_float2(acc[mi][ni][hp * 2],
                                        acc[mi][ni][hp * 2 + 1]);
                    }
                }
        });
}

// ---------------------------------------------------------------------------
// K2: flash attention, 512 threads (16 warps x m16n64), ldmatrix fragments.
// Layouts as R9 (chunked stride-36):
//   Qs[2][256][36], Ks[2][2][64][36], Vs[2][2][64][36], Ps[2][256][36]
// ---------------------------------------------------------------------------
constexpr int ATT_SMEM = (18432 + 9216 + 9216 + 18432) * (int)sizeof(float);

__device__ __forceinline__ void attn_stage_kv(
    uint32_t Ks_s, uint32_t Vs_s, int s,
    const float* __restrict__ K, const float* __restrict__ Vt,
    int kt, int tid)
{
#pragma unroll
    for (int i = 0; i < 2; i++) {
        int idx = tid + (i << 9);
        int r = idx >> 4, c4 = (idx & 15) << 2;
        const uint32_t doff =
            (uint32_t)(s * 4608 + (c4 >> 5) * 2304 + r * 36 + (c4 & 31)) * 4;
        cp16(Ks_s + doff, K + (size_t)(kt * 64 + r) * DH + c4);
        cp16(Vs_s + doff, Vt + (size_t)r * SS + kt * 64 + c4);
    }
    cp_commit();
}

__global__ __launch_bounds__(512, 1) void attn_mma()
{
    extern __shared__ float sm[];
    float* Qs = sm;               // 18432
    float* Ks = Qs + 18432;       // 9216
    float* Vs = Ks + 9216;        // 9216
    float* Ps = Vs + 9216;        // 18432
    const uint32_t Qs_s = (uint32_t)__cvta_generic_to_shared(Qs);
    const uint32_t Ks_s = (uint32_t)__cvta_generic_to_shared(Ks);
    const uint32_t Vs_s = (uint32_t)__cvta_generic_to_shared(Vs);
    const uint32_t Ps_s = (uint32_t)__cvta_generic_to_shared(Ps);

    const int qt = blockIdx.x, h = blockIdx.y, b = blockIdx.z;
    const float* __restrict__ Q  = g_q  + ((size_t)(b * HH + h) * SS + qt * 256) * DH;
    const float* __restrict__ K  = g_k  + (size_t)(b * HH + h) * SS * DH;
    const float* __restrict__ Vt = g_vt + (size_t)(b * HH + h) * DH * SS;

    const int tid = threadIdx.x;
    const int lane = tid & 31;
    const int warp = tid >> 5;     // 0..15
    const int qbase = warp * 16;   // 16 q-rows per warp

    // prologue: KV0, Q, KV1
    attn_stage_kv(Ks_s, Vs_s, 0, K, Vt, 0, tid);
#pragma unroll
    for (int i = 0; i < 8; i++) {
        int idx = tid + (i << 9);
        int r = idx >> 4, c4 = (idx & 15) << 2;
        cp16(Qs_s + (uint32_t)((c4 >> 5) * 9216 + r * 36 + (c4 & 31)) * 4,
             Q + (size_t)r * DH + c4);
    }
    cp_commit();
    attn_stage_kv(Ks_s, Vs_s, 1, K, Vt, 1, tid);

    // ldmatrix lane address bases (bytes)
    const int arow = (lane & 7) + ((lane >> 3) & 1) * 8;
    const int acol = (lane >> 4) * 4;
    const int brw = (lane & 7) + (lane >> 4) * 8;
    const int bcl = ((lane >> 3) & 1) * 4;
    const uint32_t qa = Qs_s + (uint32_t)((qbase + arow) * 36 + acol) * 4;
    const uint32_t pa = Ps_s + (uint32_t)((qbase + arow) * 36 + acol) * 4;
    const uint32_t kb = Ks_s + (uint32_t)(brw * 36 + bcl) * 4;
    const uint32_t vb = Vs_s + (uint32_t)(brw * 36 + bcl) * 4;

    float mrow[2] = {-1e30f, -1e30f};
    float lrow[2] = {0.f, 0.f};
    float o[8][4];
#pragma unroll
    for (int ni = 0; ni < 8; ni++)
#pragma unroll
        for (int f = 0; f < 4; f++) o[ni][f] = 0.f;

    constexpr int NKT = SS / 64;  // 32

    for (int kt = 0; kt < NKT; kt++) {
        if (kt + 1 < NKT) cp_wait<1>(); else cp_wait<0>();
        __syncthreads();

        const int s = kt & 1;
        const uint32_t sOff = (uint32_t)(s * 4608) * 4;

        // ---- S = Q @ K^T (m16 n64 k64 per warp) ----
        float sacc[8][4];
#pragma unroll
        for (int ni = 0; ni < 8; ni++)
#pragma unroll
            for (int f = 0; f < 4; f++) sacc[ni][f] = 0.f;

#pragma unroll
        for (int ks = 0; ks < 8; ks++) {
            const uint32_t koA = (uint32_t)((ks >> 2) * 36864 + (ks & 3) * 32);
            const uint32_t koB = (uint32_t)((ks >> 2) * 9216  + (ks & 3) * 32);
            uint32_t a[4], bf[8][2];
            ldsm4(a[0], a[1], a[2], a[3], qa + koA);
#pragma unroll
            for (int nj = 0; nj < 4; nj++)
                ldsm4(bf[2 * nj][0], bf[2 * nj][1],
                      bf[2 * nj + 1][0], bf[2 * nj + 1][1],
                      kb + sOff + koB + (uint32_t)(nj * 2304));
#pragma unroll
            for (int ni = 0; ni < 8; ni++)
                mma8(sacc[ni], a[0], a[1], a[2], a[3], bf[ni][0], bf[ni][1]);
        }

        // ---- online softmax -> Ps ----
#pragma unroll
        for (int hp = 0; hp < 2; hp++) {
            float mx = -1e30f;
#pragma unroll
            for (int ni = 0; ni < 8; ni++)
                mx = fmaxf(mx, fmaxf(sacc[ni][hp * 2], sacc[ni][hp * 2 + 1]));
            mx = fmaxf(mx, __shfl_xor_sync(0xffffffffu, mx, 1));
            mx = fmaxf(mx, __shfl_xor_sync(0xffffffffu, mx, 2));
            const float mnew = fmaxf(mrow[hp], mx);
            const float corr = __expf(mrow[hp] - mnew);
            mrow[hp] = mnew;
            float rs = 0.f;
            const int prow = qbase + hp * 8 + (lane >> 2);
#pragma unroll
            for (int ni = 0; ni < 8; ni++) {
                const float p0 = __expf(sacc[ni][hp * 2]     - mnew);
                const float p1 = __expf(sacc[ni][hp * 2 + 1] - mnew);
                rs += p0 + p1;
                const int local = (ni & 3) * 8 + 2 * (lane & 3);
                *reinterpret_cast<float2*>(
                    &Ps[(ni >> 2) * 9216 + prow * 36 + local]) =
                    make_float2(__uint_as_float(f2tf(p0)),
                                __uint_as_float(f2tf(p1)));
            }
            rs += __shfl_xor_sync(0xffffffffu, rs, 1);
            rs += __shfl_xor_sync(0xffffffffu, rs, 2);
            lrow[hp] = lrow[hp] * corr + rs;
#pragma unroll
            for (int ni = 0; ni < 8; ni++) {
                o[ni][hp * 2]     *= corr;
                o[ni][hp * 2 + 1] *= corr;
            }
        }
        __syncwarp();

        // ---- O += P @ V ----
#pragma unroll
        for (int ks = 0; ks < 8; ks++) {
            const uint32_t koA = (uint32_t)((ks >> 2) * 36864 + (ks & 3) * 32);
            const uint32_t koB = (uint32_t)((ks >> 2) * 9216  + (ks & 3) * 32);
            uint32_t a[4], bf[8][2];
            ldsm4(a[0], a[1], a[2], a[3], pa + koA);
#pragma unroll
            for (int nj = 0; nj < 4; nj++)
                ldsm4(bf[2 * nj][0], bf[2 * nj][1],
                      bf[2 * nj + 1][0], bf[2 * nj + 1][1],
                      vb + sOff + koB + (uint32_t)(nj * 2304));
#pragma unroll
            for (int ni = 0; ni < 8; ni++)
                mma8(o[ni], a[0], a[1], a[2], a[3], bf[ni][0], bf[ni][1]);
        }

        if (kt + 2 < NKT) {
            __syncthreads();
            attn_stage_kv(Ks_s, Vs_s, s, K, Vt, kt + 2, tid);
        }
    }

    // epilogue: normalize + round + write (b, s, h*64+dh)
#pragma unroll
    for (int hp = 0; hp < 2; hp++) {
        const float inv = 1.f / lrow[hp];
        const int row = qt * 256 + qbase + hp * 8 + (lane >> 2);
#pragma unroll
        for (int ni = 0; ni < 8; ni++) {
            const int col = h * 64 + ni * 8 + (lane & 3) * 2;
            *reinterpret_cast<float2*>(
                g_att + (size_t)(b * SS + row) * DD + col) =
                make_float2(__uint_as_float(f2tf(o[ni][hp * 2] * inv)),
                            __uint_as_float(f2tf(o[ni][hp * 2 + 1] * inv)));
        }
    }
}

// ---------------------------------------------------------------------------
extern "C" void kernel_launch(void* const* d_in, const int* in_sizes, int n_in,
                              void* d_out, int out_size)
{
    const float* x    = (const float*)d_in[0];
    const float* cosT = (const float*)d_in[1];
    const float* sinT = (const float*)d_in[2];
    const float* wq   = (const float*)d_in[3];
    const float* wk   = (const float*)d_in[4];
    const float* wv   = (const float*)d_in[5];
    const float* wo   = (const float*)d_in[6];
    float* out = (float*)d_out;

    static bool attr_set = false;
    if (!attr_set) {
        cudaFuncSetAttribute(qkv_mma,
                             cudaFuncAttributeMaxDynamicSharedMemorySize, GEMM_SMEM);
        cudaFuncSetAttribute(proj_mma,
                             cudaFuncAttributeMaxDynamicSharedMemorySize, GEMM_SMEM);
        cudaFuncSetAttribute(attn_mma,
                             cudaFuncAttributeMaxDynamicSharedMemorySize, ATT_SMEM);
        attr_set = true;
    }

    cvt_inputs<<<dim3(512, 5), 256>>>(x, wq, wk, wv, wo);
    qkv_mma<<<dim3(DD / 128, MT / 128, 3), 128, GEMM_SMEM>>>(cosT, sinT);
    attn_mma<<<dim3(SS / 256, HH, BB), 512, ATT_SMEM>>>();
    proj_mma<<<dim3(DD / 128, MT / 128, 1), 128, GEMM_SMEM>>>(out);
}

// round 11
// speedup vs baseline: 1.7931x; 1.7931x over previous
#include <cuda_runtime.h>
#include <cuda_fp16.h>
#include <cstdint>

// ---------------------------------------------------------------------------
// MultiHeadAttention B=2,S=2048,D=1024,H=16,Dh=64 fp32 — R11:
//  fp16 mma.sync m16n8k16 everywhere (same 10-bit mantissa as tf32, fp32 acc).
//  * GEMMs: R6 shape (4 warps, 64x64/warp), ldmatrix frags, stride-40 layout
//  * Attention: R9 shape (8 warps, m32n64), ldmatrix frags, stride-72 layout
//  * All scratch in half: g_xh, wT, q/k/vT, att
// ---------------------------------------------------------------------------

constexpr int BB = 2;
constexpr int SS = 2048;
constexpr int DD = 1024;
constexpr int HH = 16;
constexpr int DH = 64;
constexpr int MT = BB * SS;   // 4096

__device__ __half g_q[BB * HH * SS * DH];
__device__ __half g_k[BB * HH * SS * DH];
__device__ __half g_vt[BB * HH * DH * SS];   // V^T: [b,h,dh,s]
__device__ __half g_att[MT * DD];
__device__ __half g_xh[MT * DD];             // x in half
__device__ __half g_wqt[DD * DD];            // weights transposed [n][k], half
__device__ __half g_wkt[DD * DD];
__device__ __half g_wvt[DD * DD];
__device__ __half g_wot[DD * DD];

__device__ __forceinline__ uint32_t h2u(__half2 h) {
    return *reinterpret_cast<uint32_t*>(&h);
}
__device__ __forceinline__ void mma16(float* d, const uint32_t* a,
                                      const uint32_t* b) {
    asm volatile(
        "mma.sync.aligned.m16n8k16.row.col.f32.f16.f16.f32 "
        "{%0,%1,%2,%3}, {%4,%5,%6,%7}, {%8,%9}, {%0,%1,%2,%3};"
        : "+f"(d[0]), "+f"(d[1]), "+f"(d[2]), "+f"(d[3])
        : "r"(a[0]), "r"(a[1]), "r"(a[2]), "r"(a[3]), "r"(b[0]), "r"(b[1]));
}
__device__ __forceinline__ void ldsm4(uint32_t& r0, uint32_t& r1,
                                      uint32_t& r2, uint32_t& r3,
                                      uint32_t addr) {
    asm volatile(
        "ldmatrix.sync.aligned.m8n8.x4.shared.b16 {%0,%1,%2,%3}, [%4];"
        : "=r"(r0), "=r"(r1), "=r"(r2), "=r"(r3) : "r"(addr));
}
__device__ __forceinline__ void cp16(uint32_t dst, const void* src) {
    asm volatile("cp.async.cg.shared.global [%0], [%1], 16;"
                 :: "r"(dst), "l"(src));
}
__device__ __forceinline__ void cp_commit() {
    asm volatile("cp.async.commit_group;");
}
template <int N>
__device__ __forceinline__ void cp_wait() {
    asm volatile("cp.async.wait_group %0;" :: "n"(N));
}

// ---------------------------------------------------------------------------
// K0a: x -> half.  K0b: weights -> half, transposed [n][k].
// ---------------------------------------------------------------------------
__global__ __launch_bounds__(256) void cvt_xh(const float* __restrict__ x) {
    const int n4 = (MT * DD) >> 2;
    const float4* s4 = reinterpret_cast<const float4*>(x);
    uint2* d4 = reinterpret_cast<uint2*>(g_xh);
    for (int i = blockIdx.x * 256 + threadIdx.x; i < n4; i += gridDim.x * 256) {
        float4 v = s4[i];
        uint2 o;
        o.x = h2u(__floats2half2_rn(v.x, v.y));
        o.y = h2u(__floats2half2_rn(v.z, v.w));
        d4[i] = o;
    }
}

__global__ void cvt_wT(
    const float* __restrict__ wq, const float* __restrict__ wk,
    const float* __restrict__ wv, const float* __restrict__ wo) {
    __shared__ float t[32][33];
    const int z = blockIdx.z;
    const float* src = (z == 0) ? wq : (z == 1) ? wk : (z == 2) ? wv : wo;
    __half* dst = (z == 0) ? g_wqt : (z == 1) ? g_wkt : (z == 2) ? g_wvt : g_wot;
    const int tx = threadIdx.x, ty = threadIdx.y;  // 32 x 8
    const int kb = blockIdx.y * 32, nb = blockIdx.x * 32;
#pragma unroll
    for (int i = 0; i < 4; i++) {
        int k = kb + ty + i * 8;
        t[ty + i * 8][tx] = src[(size_t)k * DD + nb + tx];
    }
    __syncthreads();
#pragma unroll
    for (int i = 0; i < 4; i++) {
        int n = nb + ty + i * 8;
        dst[(size_t)n * DD + kb + tx] = __float2half_rn(t[tx][ty + i * 8]);
    }
}

// ---------------------------------------------------------------------------
// GEMM: 128x128 tile, BK=32 halves, 4 warps (2x2), 64x64/warp, 3-stage.
// Both operands K-major [128 rows][40 halves] (CF for ldmatrix: 5r mod 8).
// ---------------------------------------------------------------------------
constexpr int STW = 40;                 // smem stride in halves
constexpr int OPH = 128 * STW;          // halves per operand stage (5120)
constexpr int GEMM_SMEM = 3 * 2 * OPH * 2;  // 61440 bytes

__device__ __forceinline__ void gemm_stage(
    uint32_t As_s, uint32_t Bs_s, int s, const __half* __restrict__ A,
    const __half* __restrict__ Bt, int brow, int bcol, int kk, int tid)
{
#pragma unroll
    for (int i = 0; i < 4; i++) {
        int idx = tid + (i << 7);
        int r = idx >> 2, c8 = (idx & 3) << 3;
        const uint32_t doff = (uint32_t)(s * OPH + r * STW + c8) * 2;
        cp16(As_s + doff, A + (size_t)(brow + r) * DD + kk + c8);
        cp16(Bs_s + doff, Bt + (size_t)(bcol + r) * DD + kk + c8);
    }
    cp_commit();
}

template <typename EpiF>
__device__ __forceinline__ void gemm_run(
    char* sm, const __half* __restrict__ A, const __half* __restrict__ Bt,
    int brow, int bcol, EpiF epi)
{
    const uint32_t As_s = (uint32_t)__cvta_generic_to_shared(sm);
    const uint32_t Bs_s = As_s + 3 * OPH * 2;

    const int tid = threadIdx.x;
    const int lane = tid & 31;
    const int warp = tid >> 5;
    const int wm = warp >> 1, wn = warp & 1;

    // ldmatrix lane bases (bytes)
    const int arow = wm * 64 + (lane & 7) + ((lane >> 3) & 1) * 8;
    const int acolH = (lane >> 4) * 8;
    const int brw = wn * 64 + (lane & 7) + (lane >> 4) * 8;
    const int bcolH = ((lane >> 3) & 1) * 8;
    const uint32_t a_base = As_s + (uint32_t)(arow * STW + acolH) * 2;
    const uint32_t b_base = Bs_s + (uint32_t)(brw * STW + bcolH) * 2;

    float acc[4][8][4];
#pragma unroll
    for (int mi = 0; mi < 4; mi++)
#pragma unroll
        for (int ni = 0; ni < 8; ni++)
#pragma unroll
            for (int f = 0; f < 4; f++) acc[mi][ni][f] = 0.f;

    constexpr int NCH = DD / 32;  // 32
    gemm_stage(As_s, Bs_s, 0, A, Bt, brow, bcol, 0, tid);
    gemm_stage(As_s, Bs_s, 1, A, Bt, brow, bcol, 32, tid);

    for (int i = 0; i < NCH; i++) {
        if (i + 1 < NCH) cp_wait<1>(); else cp_wait<0>();
        __syncthreads();
        if (i + 2 < NCH)
            gemm_stage(As_s, Bs_s, (i + 2) % 3, A, Bt, brow, bcol,
                       (i + 2) * 32, tid);
        const uint32_t soff = (uint32_t)((i % 3) * OPH) * 2;
#pragma unroll
        for (int ks = 0; ks < 2; ks++) {
            const uint32_t ko = soff + (uint32_t)(ks * 16) * 2;
            uint32_t a[4][4], b[8][2];
#pragma unroll
            for (int mi = 0; mi < 4; mi++)
                ldsm4(a[mi][0], a[mi][1], a[mi][2], a[mi][3],
                      a_base + ko + (uint32_t)(mi * 16 * STW) * 2);
#pragma unroll
            for (int nj = 0; nj < 4; nj++)
                ldsm4(b[2 * nj][0], b[2 * nj][1],
                      b[2 * nj + 1][0], b[2 * nj + 1][1],
                      b_base + ko + (uint32_t)(nj * 16 * STW) * 2);
#pragma unroll
            for (int mi = 0; mi < 4; mi++)
#pragma unroll
                for (int ni = 0; ni < 8; ni++)
                    mma16(acc[mi][ni], a[mi], b[ni]);
        }
    }
    epi(acc, lane, wm, wn);
}

// ---------------------------------------------------------------------------
// K1: QKV GEMM + RoPE.  mat==2 (V): smem transpose -> g_vt[b,h,dh,s].
// ---------------------------------------------------------------------------
__global__ __launch_bounds__(128, 2) void qkv_mma(
    const float* __restrict__ cosT, const float* __restrict__ sinT)
{
    extern __shared__ char sm[];
    const int mat = blockIdx.z;
    const __half* __restrict__ w =
        (mat == 0) ? g_wqt : (mat == 1) ? g_wkt : g_wvt;
    const int brow = blockIdx.y * 128;
    const int bcol = blockIdx.x * 128;

    gemm_run(sm, g_xh, w, brow, bcol,
        [&](float acc[4][8][4], int lane, int wm, int wn) {
            const int tid = threadIdx.x;
            if (mat < 2) {
                __half* __restrict__ out = (mat == 0) ? g_q : g_k;
                const int ar = wm * 64 + (lane >> 2);
                const int ac = wn * 64 + (lane & 3) * 2;
#pragma unroll
                for (int mi = 0; mi < 4; mi++) {
#pragma unroll
                    for (int hp = 0; hp < 2; hp++) {
                        const int row = brow + ar + mi * 16 + hp * 8;
                        const int bb = row >> 11;
                        const int ss = row & (SS - 1);
#pragma unroll
                        for (int ni = 0; ni < 8; ni++) {
                            const int col = bcol + ac + ni * 8;
                            const int hh = col >> 6;
                            const int dh = col & (DH - 1);
                            float c0 = acc[mi][ni][hp * 2 + 0];
                            float c1 = acc[mi][ni][hp * 2 + 1];
                            const int fi = ss * 32 + (dh >> 1);
                            const float cs = cosT[fi], sn = sinT[fi];
                            const float o0 = c0 * cs - c1 * sn;
                            const float o1 = c0 * sn + c1 * cs;
                            c0 = o0; c1 = o1;
                            if (mat == 0) { c0 *= 0.125f; c1 *= 0.125f; }
                            *reinterpret_cast<__half2*>(
                                out + ((size_t)(bb * HH + hh) * SS + ss) * DH + dh) =
                                __floats2half2_rn(c0, c1);
                        }
                    }
                }
            } else {
                // V: transpose in smem -> g_vt[b,h,dh,s]
                __syncthreads();
                __half* T = reinterpret_cast<__half*>(sm);  // [128][136]
                const int ar = wm * 64 + (lane >> 2);
                const int ac = wn * 64 + (lane & 3) * 2;
#pragma unroll
                for (int mi = 0; mi < 4; mi++)
#pragma unroll
                    for (int hp = 0; hp < 2; hp++) {
                        const int rl = ar + mi * 16 + hp * 8;
#pragma unroll
                        for (int ni = 0; ni < 8; ni++) {
                            const int cl = ac + ni * 8;
                            T[(cl)     * 136 + rl] =
                                __float2half_rn(acc[mi][ni][hp * 2]);
                            T[(cl + 1) * 136 + rl] =
                                __float2half_rn(acc[mi][ni][hp * 2 + 1]);
                        }
                    }
                __syncthreads();
                const int bb = brow >> 11;
                const int srow = brow & (SS - 1);
#pragma unroll
                for (int i = 0; i < 16; i++) {
                    int idx = tid + (i << 7);
                    int r = idx >> 4, c8 = (idx & 15) << 3;
                    const int dhg = bcol + r;
                    const int hh = dhg >> 6, dh = dhg & 63;
                    uint4 v = *reinterpret_cast<const uint4*>(&T[r * 136 + c8]);
                    *reinterpret_cast<uint4*>(
                        g_vt + ((size_t)(bb * HH + hh) * DH + dh) * SS +
                        srow + c8) = v;
                }
            }
        });
}

// ---------------------------------------------------------------------------
// K3: output projection (half in, fp32 out)
// ---------------------------------------------------------------------------
__global__ __launch_bounds__(128, 2) void proj_mma(float* __restrict__ Cout)
{
    extern __shared__ char sm[];
    const int brow = blockIdx.y * 128;
    const int bcol = blockIdx.x * 128;

    gemm_run(sm, g_att, g_wot, brow, bcol,
        [&](float acc[4][8][4], int lane, int wm, int wn) {
            const int ar = wm * 64 + (lane >> 2);
            const int ac = wn * 64 + (lane & 3) * 2;
#pragma unroll
            for (int mi = 0; mi < 4; mi++)
#pragma unroll
                for (int hp = 0; hp < 2; hp++) {
                    const int row = brow + ar + mi * 16 + hp * 8;
#pragma unroll
                    for (int ni = 0; ni < 8; ni++) {
                        const int col = bcol + ac + ni * 8;
                        *reinterpret_cast<float2*>(
                            Cout + (size_t)row * DD + col) =
                            make_float2(acc[mi][ni][hp * 2],
                                        acc[mi][ni][hp * 2 + 1]);
                    }
                }
        });
}

// ---------------------------------------------------------------------------
// K2: flash attention, fp16 mma, 256 thr (8 warps x m32n64), 2-stage KV.
// smem halves, stride 72 (9r mod 8 -> CF):
//   Qs[256][72], Ks[2][64][72], Vs[2][64][72], Ps[256][72]  = 110592 B
// ---------------------------------------------------------------------------
constexpr int AST = 72;                     // halves
constexpr int QS_H = 256 * AST;             // 18432
constexpr int KS_H = 64 * AST;              // 4608
constexpr int ATT_SMEM = (2 * QS_H + 4 * KS_H) * 2;   // bytes

__device__ __forceinline__ void attn_stage_kv(
    uint32_t Ks_s, uint32_t Vs_s, int s,
    const __half* __restrict__ K, const __half* __restrict__ Vt,
    int kt, int tid)
{
#pragma unroll
    for (int i = 0; i < 2; i++) {
        int idx = tid + (i << 8);
        int r = idx >> 3, c8 = (idx & 7) << 3;
        const uint32_t doff = (uint32_t)(s * KS_H + r * AST + c8) * 2;
        cp16(Ks_s + doff, K + (size_t)(kt * 64 + r) * DH + c8);
        cp16(Vs_s + doff, Vt + (size_t)r * SS + kt * 64 + c8);
    }
    cp_commit();
}

__global__ __launch_bounds__(256, 1) void attn_mma()
{
    extern __shared__ char smc[];
    __half* Qs = reinterpret_cast<__half*>(smc);
    __half* Ks = Qs + QS_H;
    __half* Vs = Ks + 2 * KS_H;
    __half* Ps = Vs + 2 * KS_H;
    const uint32_t Qs_s = (uint32_t)__cvta_generic_to_shared(Qs);
    const uint32_t Ks_s = (uint32_t)__cvta_generic_to_shared(Ks);
    const uint32_t Vs_s = (uint32_t)__cvta_generic_to_shared(Vs);
    const uint32_t Ps_s = (uint32_t)__cvta_generic_to_shared(Ps);

    const int qt = blockIdx.x, h = blockIdx.y, b = blockIdx.z;
    const __half* __restrict__ Q  = g_q  + ((size_t)(b * HH + h) * SS + qt * 256) * DH;
    const __half* __restrict__ K  = g_k  + (size_t)(b * HH + h) * SS * DH;
    const __half* __restrict__ Vt = g_vt + (size_t)(b * HH + h) * DH * SS;

    const int tid = threadIdx.x;
    const int lane = tid & 31;
    const int warp = tid >> 5;
    const int qbase = warp * 32;

    // prologue: KV0, Q, KV1
    attn_stage_kv(Ks_s, Vs_s, 0, K, Vt, 0, tid);
#pragma unroll
    for (int i = 0; i < 8; i++) {
        int idx = tid + (i << 8);
        int r = idx >> 3, c8 = (idx & 7) << 3;
        cp16(Qs_s + (uint32_t)(r * AST + c8) * 2, Q + (size_t)r * DH + c8);
    }
    cp_commit();
    attn_stage_kv(Ks_s, Vs_s, 1, K, Vt, 1, tid);

    // ldmatrix lane bases (bytes)
    const int arow = (lane & 7) + ((lane >> 3) & 1) * 8;
    const int acolH = (lane >> 4) * 8;
    const int brw = (lane & 7) + (lane >> 4) * 8;
    const int bcolH = ((lane >> 3) & 1) * 8;
    const uint32_t qa = Qs_s + (uint32_t)((qbase + arow) * AST + acolH) * 2;
    const uint32_t pa = Ps_s + (uint32_t)((qbase + arow) * AST + acolH) * 2;
    const uint32_t kb = Ks_s + (uint32_t)(brw * AST + bcolH) * 2;
    const uint32_t vb = Vs_s + (uint32_t)(brw * AST + bcolH) * 2;

    float mrow[2][2], lrow[2][2];
    float o[2][8][4];
#pragma unroll
    for (int mi = 0; mi < 2; mi++)
#pragma unroll
        for (int hp = 0; hp < 2; hp++) { mrow[mi][hp] = -1e30f; lrow[mi][hp] = 0.f; }
#pragma unroll
    for (int mi = 0; mi < 2; mi++)
#pragma unroll
        for (int ni = 0; ni < 8; ni++)
#pragma unroll
            for (int f = 0; f < 4; f++) o[mi][ni][f] = 0.f;

    constexpr int NKT = SS / 64;  // 32

    for (int kt = 0; kt < NKT; kt++) {
        if (kt + 1 < NKT) cp_wait<1>(); else cp_wait<0>();
        __syncthreads();

        const int s = kt & 1;
        const uint32_t sOff = (uint32_t)(s * KS_H) * 2;

        // ---- S = Q @ K^T (m32 n64 k64 per warp, 4 k16 steps) ----
        float sacc[2][8][4];
#pragma unroll
        for (int mi = 0; mi < 2; mi++)
#pragma unroll
            for (int ni = 0; ni < 8; ni++)
#pragma unroll
                for (int f = 0; f < 4; f++) sacc[mi][ni][f] = 0.f;

#pragma unroll
        for (int ks = 0; ks < 4; ks++) {
            const uint32_t ko = (uint32_t)(ks * 16) * 2;
            uint32_t a[2][4], bf[8][2];
#pragma unroll
            for (int mi = 0; mi < 2; mi++)
                ldsm4(a[mi][0], a[mi][1], a[mi][2], a[mi][3],
                      qa + ko + (uint32_t)(mi * 16 * AST) * 2);
#pragma unroll
            for (int nj = 0; nj < 4; nj++)
                ldsm4(bf[2 * nj][0], bf[2 * nj][1],
                      bf[2 * nj + 1][0], bf[2 * nj + 1][1],
                      kb + sOff + ko + (uint32_t)(nj * 16 * AST) * 2);
#pragma unroll
            for (int mi = 0; mi < 2; mi++)
#pragma unroll
                for (int ni = 0; ni < 8; ni++)
                    mma16(sacc[mi][ni], a[mi], bf[ni]);
        }

        // ---- online softmax -> Ps (half) ----
#pragma unroll
        for (int mi = 0; mi < 2; mi++) {
#pragma unroll
            for (int hp = 0; hp < 2; hp++) {
                float mx = -1e30f;
#pragma unroll
                for (int ni = 0; ni < 8; ni++)
                    mx = fmaxf(mx, fmaxf(sacc[mi][ni][hp * 2],
                                         sacc[mi][ni][hp * 2 + 1]));
                mx = fmaxf(mx, __shfl_xor_sync(0xffffffffu, mx, 1));
                mx = fmaxf(mx, __shfl_xor_sync(0xffffffffu, mx, 2));
                const float mnew = fmaxf(mrow[mi][hp], mx);
                const float corr = __expf(mrow[mi][hp] - mnew);
                mrow[mi][hp] = mnew;
                float rs = 0.f;
                const int prow = qbase + mi * 16 + hp * 8 + (lane >> 2);
#pragma unroll
                for (int ni = 0; ni < 8; ni++) {
                    const float p0 = __expf(sacc[mi][ni][hp * 2]     - mnew);
                    const float p1 = __expf(sacc[mi][ni][hp * 2 + 1] - mnew);
                    rs += p0 + p1;
                    *reinterpret_cast<__half2*>(
                        &Ps[prow * AST + ni * 8 + 2 * (lane & 3)]) =
                        __floats2half2_rn(p0, p1);
                }
                rs += __shfl_xor_sync(0xffffffffu, rs, 1);
                rs += __shfl_xor_sync(0xffffffffu, rs, 2);
                lrow[mi][hp] = lrow[mi][hp] * corr + rs;
#pragma unroll
                for (int ni = 0; ni < 8; ni++) {
                    o[mi][ni][hp * 2]     *= corr;
                    o[mi][ni][hp * 2 + 1] *= corr;
                }
            }
        }
        __syncwarp();

        // ---- O += P @ V (A=P, B=V^T) ----
#pragma unroll
        for (int ks = 0; ks < 4; ks++) {
            const uint32_t ko = (uint32_t)(ks * 16) * 2;
            uint32_t a[2][4], bf[8][2];
#pragma unroll
            for (int mi = 0; mi < 2; mi++)
                ldsm4(a[mi][0], a[mi][1], a[mi][2], a[mi][3],
                      pa + ko + (uint32_t)(mi * 16 * AST) * 2);
#pragma unroll
            for (int nj = 0; nj < 4; nj++)
                ldsm4(bf[2 * nj][0], bf[2 * nj][1],
                      bf[2 * nj + 1][0], bf[2 * nj + 1][1],
                      vb + sOff + ko + (uint32_t)(nj * 16 * AST) * 2);
#pragma unroll
            for (int mi = 0; mi < 2; mi++)
#pragma unroll
                for (int ni = 0; ni < 8; ni++)
                    mma16(o[mi][ni], a[mi], bf[ni]);
        }

        if (kt + 2 < NKT) {
            __syncthreads();
            attn_stage_kv(Ks_s, Vs_s, s, K, Vt, kt + 2, tid);
        }
    }

    // epilogue: normalize + write half (b, s, h*64+dh)
#pragma unroll
    for (int mi = 0; mi < 2; mi++)
#pragma unroll
        for (int hp = 0; hp < 2; hp++) {
            const float inv = 1.f / lrow[mi][hp];
            const int row = qt * 256 + qbase + mi * 16 + hp * 8 + (lane >> 2);
#pragma unroll
            for (int ni = 0; ni < 8; ni++) {
                const int col = h * 64 + ni * 8 + (lane & 3) * 2;
                *reinterpret_cast<__half2*>(
                    g_att + (size_t)(b * SS + row) * DD + col) =
                    __floats2half2_rn(o[mi][ni][hp * 2] * inv,
                                      o[mi][ni][hp * 2 + 1] * inv);
            }
        }
}

// ---------------------------------------------------------------------------
extern "C" void kernel_launch(void* const* d_in, const int* in_sizes, int n_in,
                              void* d_out, int out_size)
{
    const float* x    = (const float*)d_in[0];
    const float* cosT = (const float*)d_in[1];
    const float* sinT = (const float*)d_in[2];
    const float* wq   = (const float*)d_in[3];
    const float* wk   = (const float*)d_in[4];
    const float* wv   = (const float*)d_in[5];
    const float* wo   = (const float*)d_in[6];
    float* out = (float*)d_out;

    static bool attr_set = false;
    if (!attr_set) {
        cudaFuncSetAttribute(qkv_mma,
                             cudaFuncAttributeMaxDynamicSharedMemorySize, GEMM_SMEM);
        cudaFuncSetAttribute(proj_mma,
                             cudaFuncAttributeMaxDynamicSharedMemorySize, GEMM_SMEM);
        cudaFuncSetAttribute(attn_mma,
                             cudaFuncAttributeMaxDynamicSharedMemorySize, ATT_SMEM);
        attr_set = true;
    }

    cvt_xh<<<256, 256>>>(x);
    cvt_wT<<<dim3(32, 32, 4), dim3(32, 8)>>>(wq, wk, wv, wo);
    qkv_mma<<<dim3(DD / 128, MT / 128, 3), 128, GEMM_SMEM>>>(cosT, sinT);
    attn_mma<<<dim3(SS / 256, HH, BB), 256, ATT_SMEM>>>();
    proj_mma<<<dim3(DD / 128, MT / 128, 1), 128, GEMM_SMEM>>>(out);
}

// round 12
// speedup vs baseline: 1.8894x; 1.0537x over previous
#include <cuda_runtime.h>
#include <cuda_fp16.h>
#include <cstdint>

// ---------------------------------------------------------------------------
// MultiHeadAttention B=2,S=2048,D=1024,H=16,Dh=64 fp32 — R12:
//  fp16 mma pipeline (R11) + softmax offload:
//   * PV ones-column computes row-sums l on the tensor pipe
//   * p = ex2.approx.f16x2 (half2 exp), consistent with mma operands
// ---------------------------------------------------------------------------

constexpr int BB = 2;
constexpr int SS = 2048;
constexpr int DD = 1024;
constexpr int HH = 16;
constexpr int DH = 64;
constexpr int MT = BB * SS;   // 4096

__device__ __half g_q[BB * HH * SS * DH];
__device__ __half g_k[BB * HH * SS * DH];
__device__ __half g_vt[BB * HH * DH * SS];   // V^T: [b,h,dh,s]
__device__ __half g_att[MT * DD];
__device__ __half g_xh[MT * DD];
__device__ __half g_wqt[DD * DD];            // weights transposed [n][k]
__device__ __half g_wkt[DD * DD];
__device__ __half g_wvt[DD * DD];
__device__ __half g_wot[DD * DD];

__device__ __forceinline__ uint32_t h2u(__half2 h) {
    return *reinterpret_cast<uint32_t*>(&h);
}
__device__ __forceinline__ uint32_t h2exp2(uint32_t x) {
    uint32_t r;
    asm("ex2.approx.f16x2 %0, %1;" : "=r"(r) : "r"(x));
    return r;
}
__device__ __forceinline__ void mma16(float* d, const uint32_t* a,
                                      const uint32_t* b) {
    asm volatile(
        "mma.sync.aligned.m16n8k16.row.col.f32.f16.f16.f32 "
        "{%0,%1,%2,%3}, {%4,%5,%6,%7}, {%8,%9}, {%0,%1,%2,%3};"
        : "+f"(d[0]), "+f"(d[1]), "+f"(d[2]), "+f"(d[3])
        : "r"(a[0]), "r"(a[1]), "r"(a[2]), "r"(a[3]), "r"(b[0]), "r"(b[1]));
}
__device__ __forceinline__ void ldsm4(uint32_t& r0, uint32_t& r1,
                                      uint32_t& r2, uint32_t& r3,
                                      uint32_t addr) {
    asm volatile(
        "ldmatrix.sync.aligned.m8n8.x4.shared.b16 {%0,%1,%2,%3}, [%4];"
        : "=r"(r0), "=r"(r1), "=r"(r2), "=r"(r3) : "r"(addr));
}
__device__ __forceinline__ void cp16(uint32_t dst, const void* src) {
    asm volatile("cp.async.cg.shared.global [%0], [%1], 16;"
                 :: "r"(dst), "l"(src));
}
__device__ __forceinline__ void cp_commit() {
    asm volatile("cp.async.commit_group;");
}
template <int N>
__device__ __forceinline__ void cp_wait() {
    asm volatile("cp.async.wait_group %0;" :: "n"(N));
}

// ---------------------------------------------------------------------------
// K0a: x -> half.  K0b: weights -> half, transposed [n][k].
// ---------------------------------------------------------------------------
__global__ __launch_bounds__(256) void cvt_xh(const float* __restrict__ x) {
    const int n4 = (MT * DD) >> 2;
    const float4* s4 = reinterpret_cast<const float4*>(x);
    uint2* d4 = reinterpret_cast<uint2*>(g_xh);
    for (int i = blockIdx.x * 256 + threadIdx.x; i < n4; i += gridDim.x * 256) {
        float4 v = s4[i];
        uint2 o;
        o.x = h2u(__floats2half2_rn(v.x, v.y));
        o.y = h2u(__floats2half2_rn(v.z, v.w));
        d4[i] = o;
    }
}

__global__ void cvt_wT(
    const float* __restrict__ wq, const float* __restrict__ wk,
    const float* __restrict__ wv, const float* __restrict__ wo) {
    __shared__ float t[32][33];
    const int z = blockIdx.z;
    const float* src = (z == 0) ? wq : (z == 1) ? wk : (z == 2) ? wv : wo;
    __half* dst = (z == 0) ? g_wqt : (z == 1) ? g_wkt : (z == 2) ? g_wvt : g_wot;
    const int tx = threadIdx.x, ty = threadIdx.y;
    const int kb = blockIdx.y * 32, nb = blockIdx.x * 32;
#pragma unroll
    for (int i = 0; i < 4; i++) {
        int k = kb + ty + i * 8;
        t[ty + i * 8][tx] = src[(size_t)k * DD + nb + tx];
    }
    __syncthreads();
#pragma unroll
    for (int i = 0; i < 4; i++) {
        int n = nb + ty + i * 8;
        dst[(size_t)n * DD + kb + tx] = __float2half_rn(t[tx][ty + i * 8]);
    }
}

// ---------------------------------------------------------------------------
// GEMM (R11): 128x128 tile, BK=32 halves, 4 warps, 64x64/warp, 3-stage.
// ---------------------------------------------------------------------------
constexpr int STW = 40;
constexpr int OPH = 128 * STW;
constexpr int GEMM_SMEM = 3 * 2 * OPH * 2;

__device__ __forceinline__ void gemm_stage(
    uint32_t As_s, uint32_t Bs_s, int s, const __half* __restrict__ A,
    const __half* __restrict__ Bt, int brow, int bcol, int kk, int tid)
{
#pragma unroll
    for (int i = 0; i < 4; i++) {
        int idx = tid + (i << 7);
        int r = idx >> 2, c8 = (idx & 3) << 3;
        const uint32_t doff = (uint32_t)(s * OPH + r * STW + c8) * 2;
        cp16(As_s + doff, A + (size_t)(brow + r) * DD + kk + c8);
        cp16(Bs_s + doff, Bt + (size_t)(bcol + r) * DD + kk + c8);
    }
    cp_commit();
}

template <typename EpiF>
__device__ __forceinline__ void gemm_run(
    char* sm, const __half* __restrict__ A, const __half* __restrict__ Bt,
    int brow, int bcol, EpiF epi)
{
    const uint32_t As_s = (uint32_t)__cvta_generic_to_shared(sm);
    const uint32_t Bs_s = As_s + 3 * OPH * 2;

    const int tid = threadIdx.x;
    const int lane = tid & 31;
    const int warp = tid >> 5;
    const int wm = warp >> 1, wn = warp & 1;

    const int arow = wm * 64 + (lane & 7) + ((lane >> 3) & 1) * 8;
    const int acolH = (lane >> 4) * 8;
    const int brw = wn * 64 + (lane & 7) + (lane >> 4) * 8;
    const int bcolH = ((lane >> 3) & 1) * 8;
    const uint32_t a_base = As_s + (uint32_t)(arow * STW + acolH) * 2;
    const uint32_t b_base = Bs_s + (uint32_t)(brw * STW + bcolH) * 2;

    float acc[4][8][4];
#pragma unroll
    for (int mi = 0; mi < 4; mi++)
#pragma unroll
        for (int ni = 0; ni < 8; ni++)
#pragma unroll
            for (int f = 0; f < 4; f++) acc[mi][ni][f] = 0.f;

    constexpr int NCH = DD / 32;
    gemm_stage(As_s, Bs_s, 0, A, Bt, brow, bcol, 0, tid);
    gemm_stage(As_s, Bs_s, 1, A, Bt, brow, bcol, 32, tid);

    for (int i = 0; i < NCH; i++) {
        if (i + 1 < NCH) cp_wait<1>(); else cp_wait<0>();
        __syncthreads();
        if (i + 2 < NCH)
            gemm_stage(As_s, Bs_s, (i + 2) % 3, A, Bt, brow, bcol,
                       (i + 2) * 32, tid);
        const uint32_t soff = (uint32_t)((i % 3) * OPH) * 2;
#pragma unroll
        for (int ks = 0; ks < 2; ks++) {
            const uint32_t ko = soff + (uint32_t)(ks * 16) * 2;
            uint32_t a[4][4], b[8][2];
#pragma unroll
            for (int mi = 0; mi < 4; mi++)
                ldsm4(a[mi][0], a[mi][1], a[mi][2], a[mi][3],
                      a_base + ko + (uint32_t)(mi * 16 * STW) * 2);
#pragma unroll
            for (int nj = 0; nj < 4; nj++)
                ldsm4(b[2 * nj][0], b[2 * nj][1],
                      b[2 * nj + 1][0], b[2 * nj + 1][1],
                      b_base + ko + (uint32_t)(nj * 16 * STW) * 2);
#pragma unroll
            for (int mi = 0; mi < 4; mi++)
#pragma unroll
                for (int ni = 0; ni < 8; ni++)
                    mma16(acc[mi][ni], a[mi], b[ni]);
        }
    }
    epi(acc, lane, wm, wn);
}

// ---------------------------------------------------------------------------
// K1: QKV GEMM + RoPE.  mat==2 (V): smem transpose -> g_vt[b,h,dh,s].
// ---------------------------------------------------------------------------
__global__ __launch_bounds__(128, 2) void qkv_mma(
    const float* __restrict__ cosT, const float* __restrict__ sinT)
{
    extern __shared__ char sm[];
    const int mat = blockIdx.z;
    const __half* __restrict__ w =
        (mat == 0) ? g_wqt : (mat == 1) ? g_wkt : g_wvt;
    const int brow = blockIdx.y * 128;
    const int bcol = blockIdx.x * 128;

    gemm_run(sm, g_xh, w, brow, bcol,
        [&](float acc[4][8][4], int lane, int wm, int wn) {
            const int tid = threadIdx.x;
            if (mat < 2) {
                __half* __restrict__ out = (mat == 0) ? g_q : g_k;
                const int ar = wm * 64 + (lane >> 2);
                const int ac = wn * 64 + (lane & 3) * 2;
#pragma unroll
                for (int mi = 0; mi < 4; mi++) {
#pragma unroll
                    for (int hp = 0; hp < 2; hp++) {
                        const int row = brow + ar + mi * 16 + hp * 8;
                        const int bb = row >> 11;
                        const int ss = row & (SS - 1);
#pragma unroll
                        for (int ni = 0; ni < 8; ni++) {
                            const int col = bcol + ac + ni * 8;
                            const int hh = col >> 6;
                            const int dh = col & (DH - 1);
                            float c0 = acc[mi][ni][hp * 2 + 0];
                            float c1 = acc[mi][ni][hp * 2 + 1];
                            const int fi = ss * 32 + (dh >> 1);
                            const float cs = cosT[fi], sn = sinT[fi];
                            const float o0 = c0 * cs - c1 * sn;
                            const float o1 = c0 * sn + c1 * cs;
                            c0 = o0; c1 = o1;
                            if (mat == 0) { c0 *= 0.125f; c1 *= 0.125f; }
                            *reinterpret_cast<__half2*>(
                                out + ((size_t)(bb * HH + hh) * SS + ss) * DH + dh) =
                                __floats2half2_rn(c0, c1);
                        }
                    }
                }
            } else {
                __syncthreads();
                __half* T = reinterpret_cast<__half*>(sm);  // [128][136]
                const int ar = wm * 64 + (lane >> 2);
                const int ac = wn * 64 + (lane & 3) * 2;
#pragma unroll
                for (int mi = 0; mi < 4; mi++)
#pragma unroll
                    for (int hp = 0; hp < 2; hp++) {
                        const int rl = ar + mi * 16 + hp * 8;
#pragma unroll
                        for (int ni = 0; ni < 8; ni++) {
                            const int cl = ac + ni * 8;
                            T[(cl)     * 136 + rl] =
                                __float2half_rn(acc[mi][ni][hp * 2]);
                            T[(cl + 1) * 136 + rl] =
                                __float2half_rn(acc[mi][ni][hp * 2 + 1]);
                        }
                    }
                __syncthreads();
                const int bb = brow >> 11;
                const int srow = brow & (SS - 1);
#pragma unroll
                for (int i = 0; i < 16; i++) {
                    int idx = tid + (i << 7);
                    int r = idx >> 4, c8 = (idx & 15) << 3;
                    const int dhg = bcol + r;
                    const int hh = dhg >> 6, dh = dhg & 63;
                    uint4 v = *reinterpret_cast<const uint4*>(&T[r * 136 + c8]);
                    *reinterpret_cast<uint4*>(
                        g_vt + ((size_t)(bb * HH + hh) * DH + dh) * SS +
                        srow + c8) = v;
                }
            }
        });
}

// ---------------------------------------------------------------------------
// K3: output projection (half in, fp32 out)
// ---------------------------------------------------------------------------
__global__ __launch_bounds__(128, 2) void proj_mma(float* __restrict__ Cout)
{
    extern __shared__ char sm[];
    const int brow = blockIdx.y * 128;
    const int bcol = blockIdx.x * 128;

    gemm_run(sm, g_att, g_wot, brow, bcol,
        [&](float acc[4][8][4], int lane, int wm, int wn) {
            const int ar = wm * 64 + (lane >> 2);
            const int ac = wn * 64 + (lane & 3) * 2;
#pragma unroll
            for (int mi = 0; mi < 4; mi++)
#pragma unroll
                for (int hp = 0; hp < 2; hp++) {
                    const int row = brow + ar + mi * 16 + hp * 8;
#pragma unroll
                    for (int ni = 0; ni < 8; ni++) {
                        const int col = bcol + ac + ni * 8;
                        *reinterpret_cast<float2*>(
                            Cout + (size_t)row * DD + col) =
                            make_float2(acc[mi][ni][hp * 2],
                                        acc[mi][ni][hp * 2 + 1]);
                    }
                }
        });
}

// ---------------------------------------------------------------------------
// K2: flash attention, fp16 mma, 256 thr (8 warps x m32n64), 2-stage KV.
// Vs has 80 rows: rows 0-63 = V^T data, row 64 = ones (row-sum column),
// rows 65-79 = zeros.  l comes out of the PV mma as fragment ni=8.
// ---------------------------------------------------------------------------
constexpr int AST = 72;                     // halves
constexpr int QS_H = 256 * AST;             // 18432
constexpr int KS_H = 64 * AST;              // 4608
constexpr int VS_H = 80 * AST;              // 5760
constexpr int ATT_SMEM = (2 * QS_H + 2 * KS_H + 2 * VS_H) * 2;  // 115200 B

__device__ __forceinline__ void attn_stage_kv(
    uint32_t Ks_s, uint32_t Vs_s, int s,
    const __half* __restrict__ K, const __half* __restrict__ Vt,
    int kt, int tid)
{
#pragma unroll
    for (int i = 0; i < 2; i++) {
        int idx = tid + (i << 8);
        int r = idx >> 3, c8 = (idx & 7) << 3;
        cp16(Ks_s + (uint32_t)(s * KS_H + r * AST + c8) * 2,
             K + (size_t)(kt * 64 + r) * DH + c8);
        cp16(Vs_s + (uint32_t)(s * VS_H + r * AST + c8) * 2,
             Vt + (size_t)r * SS + kt * 64 + c8);
    }
    cp_commit();
}

__global__ __launch_bounds__(256, 1) void attn_mma()
{
    extern __shared__ char smc[];
    __half* Qs = reinterpret_cast<__half*>(smc);
    __half* Ks = Qs + QS_H;
    __half* Vs = Ks + 2 * KS_H;
    __half* Ps = Vs + 2 * VS_H;
    const uint32_t Qs_s = (uint32_t)__cvta_generic_to_shared(Qs);
    const uint32_t Ks_s = (uint32_t)__cvta_generic_to_shared(Ks);
    const uint32_t Vs_s = (uint32_t)__cvta_generic_to_shared(Vs);
    const uint32_t Ps_s = (uint32_t)__cvta_generic_to_shared(Ps);

    const int qt = blockIdx.x, h = blockIdx.y, b = blockIdx.z;
    const __half* __restrict__ Q  = g_q  + ((size_t)(b * HH + h) * SS + qt * 256) * DH;
    const __half* __restrict__ K  = g_k  + (size_t)(b * HH + h) * SS * DH;
    const __half* __restrict__ Vt = g_vt + (size_t)(b * HH + h) * DH * SS;

    const int tid = threadIdx.x;
    const int lane = tid & 31;
    const int warp = tid >> 5;
    const int qbase = warp * 32;

    // prologue: KV0, Q, KV1; ones/zeros rows of Vs (both stages)
    attn_stage_kv(Ks_s, Vs_s, 0, K, Vt, 0, tid);
#pragma unroll
    for (int i = 0; i < 8; i++) {
        int idx = tid + (i << 8);
        int r = idx >> 3, c8 = (idx & 7) << 3;
        cp16(Qs_s + (uint32_t)(r * AST + c8) * 2, Q + (size_t)r * DH + c8);
    }
    cp_commit();
    attn_stage_kv(Ks_s, Vs_s, 1, K, Vt, 1, tid);

    for (int idx = tid; idx < 2 * 16 * AST; idx += 256) {
        const int s = idx / (16 * AST);
        const int rem = idx % (16 * AST);
        const int r = 64 + rem / AST;
        const int c = rem % AST;
        Vs[s * VS_H + r * AST + c] =
            (r == 64) ? __float2half(1.f) : __float2half(0.f);
    }

    // ldmatrix lane bases (bytes)
    const int arow = (lane & 7) + ((lane >> 3) & 1) * 8;
    const int acolH = (lane >> 4) * 8;
    const int brw = (lane & 7) + (lane >> 4) * 8;
    const int bcolH = ((lane >> 3) & 1) * 8;
    const uint32_t qa = Qs_s + (uint32_t)((qbase + arow) * AST + acolH) * 2;
    const uint32_t pa = Ps_s + (uint32_t)((qbase + arow) * AST + acolH) * 2;
    const uint32_t kb = Ks_s + (uint32_t)(brw * AST + bcolH) * 2;
    const uint32_t vb = Vs_s + (uint32_t)(brw * AST + bcolH) * 2;

    constexpr float L2E = 1.4426950408889634f;

    float mrow[2][2];
    float o[2][9][4];   // ni=8 is the row-sum (l) column
#pragma unroll
    for (int mi = 0; mi < 2; mi++) {
#pragma unroll
        for (int hp = 0; hp < 2; hp++) mrow[mi][hp] = -1e30f;
#pragma unroll
        for (int ni = 0; ni < 9; ni++)
#pragma unroll
            for (int f = 0; f < 4; f++) o[mi][ni][f] = 0.f;
    }

    constexpr int NKT = SS / 64;  // 32

    for (int kt = 0; kt < NKT; kt++) {
        if (kt + 1 < NKT) cp_wait<1>(); else cp_wait<0>();
        __syncthreads();

        const int s = kt & 1;
        const uint32_t kOff = (uint32_t)(s * KS_H) * 2;
        const uint32_t vOff = (uint32_t)(s * VS_H) * 2;

        // ---- S = Q @ K^T ----
        float sacc[2][8][4];
#pragma unroll
        for (int mi = 0; mi < 2; mi++)
#pragma unroll
            for (int ni = 0; ni < 8; ni++)
#pragma unroll
                for (int f = 0; f < 4; f++) sacc[mi][ni][f] = 0.f;

#pragma unroll
        for (int ks = 0; ks < 4; ks++) {
            const uint32_t ko = (uint32_t)(ks * 16) * 2;
            uint32_t a[2][4], bf[8][2];
#pragma unroll
            for (int mi = 0; mi < 2; mi++)
                ldsm4(a[mi][0], a[mi][1], a[mi][2], a[mi][3],
                      qa + ko + (uint32_t)(mi * 16 * AST) * 2);
#pragma unroll
            for (int nj = 0; nj < 4; nj++)
                ldsm4(bf[2 * nj][0], bf[2 * nj][1],
                      bf[2 * nj + 1][0], bf[2 * nj + 1][1],
                      kb + kOff + ko + (uint32_t)(nj * 16 * AST) * 2);
#pragma unroll
            for (int mi = 0; mi < 2; mi++)
#pragma unroll
                for (int ni = 0; ni < 8; ni++)
                    mma16(sacc[mi][ni], a[mi], bf[ni]);
        }

        // ---- online softmax -> Ps (half2 ex2; sums via PV ones-column) ----
#pragma unroll
        for (int mi = 0; mi < 2; mi++) {
#pragma unroll
            for (int hp = 0; hp < 2; hp++) {
                float mx = -1e30f;
#pragma unroll
                for (int ni = 0; ni < 8; ni++)
                    mx = fmaxf(mx, fmaxf(sacc[mi][ni][hp * 2],
                                         sacc[mi][ni][hp * 2 + 1]));
                mx = fmaxf(mx, __shfl_xor_sync(0xffffffffu, mx, 1));
                mx = fmaxf(mx, __shfl_xor_sync(0xffffffffu, mx, 2));
                const float mnew = fmaxf(mrow[mi][hp], mx);
                const float corr = __expf(mrow[mi][hp] - mnew);
                mrow[mi][hp] = mnew;
                const float mL2 = mnew * L2E;
                const int prow = qbase + mi * 16 + hp * 8 + (lane >> 2);
#pragma unroll
                for (int ni = 0; ni < 8; ni++) {
                    const float b0 = fmaf(sacc[mi][ni][hp * 2],     L2E, -mL2);
                    const float b1 = fmaf(sacc[mi][ni][hp * 2 + 1], L2E, -mL2);
                    const uint32_t pp = h2exp2(h2u(__floats2half2_rn(b0, b1)));
                    *reinterpret_cast<uint32_t*>(
                        &Ps[prow * AST + ni * 8 + 2 * (lane & 3)]) = pp;
                }
#pragma unroll
                for (int ni = 0; ni < 9; ni++) {
                    o[mi][ni][hp * 2]     *= corr;
                    o[mi][ni][hp * 2 + 1] *= corr;
                }
            }
        }
        __syncwarp();

        // ---- O += P @ [V^T ; ones] ----
#pragma unroll
        for (int ks = 0; ks < 4; ks++) {
            const uint32_t ko = (uint32_t)(ks * 16) * 2;
            uint32_t a[2][4], bf[10][2];
#pragma unroll
            for (int mi = 0; mi < 2; mi++)
                ldsm4(a[mi][0], a[mi][1], a[mi][2], a[mi][3],
                      pa + ko + (uint32_t)(mi * 16 * AST) * 2);
#pragma unroll
            for (int nj = 0; nj < 5; nj++)
                ldsm4(bf[2 * nj][0], bf[2 * nj][1],
                      bf[2 * nj + 1][0], bf[2 * nj + 1][1],
                      vb + vOff + ko + (uint32_t)(nj * 16 * AST) * 2);
#pragma unroll
            for (int mi = 0; mi < 2; mi++)
#pragma unroll
                for (int ni = 0; ni < 9; ni++)
                    mma16(o[mi][ni], a[mi], bf[ni]);
        }

        if (kt + 2 < NKT) {
            __syncthreads();
            attn_stage_kv(Ks_s, Vs_s, s, K, Vt, kt + 2, tid);
        }
    }

    // epilogue: l from ones-column (quad lane 0), normalize, write half
#pragma unroll
    for (int mi = 0; mi < 2; mi++)
#pragma unroll
        for (int hp = 0; hp < 2; hp++) {
            const float l = __shfl_sync(0xffffffffu, o[mi][8][hp * 2],
                                        lane & ~3);
            const float inv = 1.f / l;
            const int row = qt * 256 + qbase + mi * 16 + hp * 8 + (lane >> 2);
#pragma unroll
            for (int ni = 0; ni < 8; ni++) {
                const int col = h * 64 + ni * 8 + (lane & 3) * 2;
                *reinterpret_cast<__half2*>(
                    g_att + (size_t)(b * SS + row) * DD + col) =
                    __floats2half2_rn(o[mi][ni][hp * 2] * inv,
                                      o[mi][ni][hp * 2 + 1] * inv);
            }
        }
}

// ---------------------------------------------------------------------------
extern "C" void kernel_launch(void* const* d_in, const int* in_sizes, int n_in,
                              void* d_out, int out_size)
{
    const float* x    = (const float*)d_in[0];
    const float* cosT = (const float*)d_in[1];
    const float* sinT = (const float*)d_in[2];
    const float* wq   = (const float*)d_in[3];
    const float* wk   = (const float*)d_in[4];
    const float* wv   = (const float*)d_in[5];
    const float* wo   = (const float*)d_in[6];
    float* out = (float*)d_out;

    static bool attr_set = false;
    if (!attr_set) {
        cudaFuncSetAttribute(qkv_mma,
                             cudaFuncAttributeMaxDynamicSharedMemorySize, GEMM_SMEM);
        cudaFuncSetAttribute(proj_mma,
                             cudaFuncAttributeMaxDynamicSharedMemorySize, GEMM_SMEM);
        cudaFuncSetAttribute(attn_mma,
                             cudaFuncAttributeMaxDynamicSharedMemorySize, ATT_SMEM);
        attr_set = true;
    }

    cvt_xh<<<256, 256>>>(x);
    cvt_wT<<<dim3(32, 32, 4), dim3(32, 8)>>>(wq, wk, wv, wo);
    qkv_mma<<<dim3(DD / 128, MT / 128, 3), 128, GEMM_SMEM>>>(cosT, sinT);
    attn_mma<<<dim3(SS / 256, HH, BB), 256, ATT_SMEM>>>();
    proj_mma<<<dim3(DD / 128, MT / 128, 1), 128, GEMM_SMEM>>>(out);
}

// round 13
// speedup vs baseline: 1.9969x; 1.0569x over previous
#include <cuda_runtime.h>
#include <cuda_fp16.h>
#include <cstdint>

// ---------------------------------------------------------------------------
// MultiHeadAttention B=2,S=2048,D=1024,H=16,Dh=64 fp32 — R13:
//  R12 pipeline + attention re-blocked: 128 q-rows, 4 warps, 78KB smem
//  -> 2 blocks/SM (two KV pipelines per SM overlap softmax with mma).
// ---------------------------------------------------------------------------

constexpr int BB = 2;
constexpr int SS = 2048;
constexpr int DD = 1024;
constexpr int HH = 16;
constexpr int DH = 64;
constexpr int MT = BB * SS;   // 4096

__device__ __half g_q[BB * HH * SS * DH];
__device__ __half g_k[BB * HH * SS * DH];
__device__ __half g_vt[BB * HH * DH * SS];   // V^T: [b,h,dh,s]
__device__ __half g_att[MT * DD];
__device__ __half g_xh[MT * DD];
__device__ __half g_wqt[DD * DD];            // weights transposed [n][k]
__device__ __half g_wkt[DD * DD];
__device__ __half g_wvt[DD * DD];
__device__ __half g_wot[DD * DD];

__device__ __forceinline__ uint32_t h2u(__half2 h) {
    return *reinterpret_cast<uint32_t*>(&h);
}
__device__ __forceinline__ uint32_t h2exp2(uint32_t x) {
    uint32_t r;
    asm("ex2.approx.f16x2 %0, %1;" : "=r"(r) : "r"(x));
    return r;
}
__device__ __forceinline__ void mma16(float* d, const uint32_t* a,
                                      const uint32_t* b) {
    asm volatile(
        "mma.sync.aligned.m16n8k16.row.col.f32.f16.f16.f32 "
        "{%0,%1,%2,%3}, {%4,%5,%6,%7}, {%8,%9}, {%0,%1,%2,%3};"
        : "+f"(d[0]), "+f"(d[1]), "+f"(d[2]), "+f"(d[3])
        : "r"(a[0]), "r"(a[1]), "r"(a[2]), "r"(a[3]), "r"(b[0]), "r"(b[1]));
}
__device__ __forceinline__ void ldsm4(uint32_t& r0, uint32_t& r1,
                                      uint32_t& r2, uint32_t& r3,
                                      uint32_t addr) {
    asm volatile(
        "ldmatrix.sync.aligned.m8n8.x4.shared.b16 {%0,%1,%2,%3}, [%4];"
        : "=r"(r0), "=r"(r1), "=r"(r2), "=r"(r3) : "r"(addr));
}
__device__ __forceinline__ void cp16(uint32_t dst, const void* src) {
    asm volatile("cp.async.cg.shared.global [%0], [%1], 16;"
                 :: "r"(dst), "l"(src));
}
__device__ __forceinline__ void cp_commit() {
    asm volatile("cp.async.commit_group;");
}
template <int N>
__device__ __forceinline__ void cp_wait() {
    asm volatile("cp.async.wait_group %0;" :: "n"(N));
}

// ---------------------------------------------------------------------------
// K0a: x -> half.  K0b: weights -> half, transposed [n][k].
// ---------------------------------------------------------------------------
__global__ __launch_bounds__(256) void cvt_xh(const float* __restrict__ x) {
    const int n4 = (MT * DD) >> 2;
    const float4* s4 = reinterpret_cast<const float4*>(x);
    uint2* d4 = reinterpret_cast<uint2*>(g_xh);
    for (int i = blockIdx.x * 256 + threadIdx.x; i < n4; i += gridDim.x * 256) {
        float4 v = s4[i];
        uint2 o;
        o.x = h2u(__floats2half2_rn(v.x, v.y));
        o.y = h2u(__floats2half2_rn(v.z, v.w));
        d4[i] = o;
    }
}

__global__ void cvt_wT(
    const float* __restrict__ wq, const float* __restrict__ wk,
    const float* __restrict__ wv, const float* __restrict__ wo) {
    __shared__ float t[32][33];
    const int z = blockIdx.z;
    const float* src = (z == 0) ? wq : (z == 1) ? wk : (z == 2) ? wv : wo;
    __half* dst = (z == 0) ? g_wqt : (z == 1) ? g_wkt : (z == 2) ? g_wvt : g_wot;
    const int tx = threadIdx.x, ty = threadIdx.y;
    const int kb = blockIdx.y * 32, nb = blockIdx.x * 32;
#pragma unroll
    for (int i = 0; i < 4; i++) {
        int k = kb + ty + i * 8;
        t[ty + i * 8][tx] = src[(size_t)k * DD + nb + tx];
    }
    __syncthreads();
#pragma unroll
    for (int i = 0; i < 4; i++) {
        int n = nb + ty + i * 8;
        dst[(size_t)n * DD + kb + tx] = __float2half_rn(t[tx][ty + i * 8]);
    }
}

// ---------------------------------------------------------------------------
// GEMM (R11): 128x128 tile, BK=32 halves, 4 warps, 64x64/warp, 3-stage.
// ---------------------------------------------------------------------------
constexpr int STW = 40;
constexpr int OPH = 128 * STW;
constexpr int GEMM_SMEM = 3 * 2 * OPH * 2;

__device__ __forceinline__ void gemm_stage(
    uint32_t As_s, uint32_t Bs_s, int s, const __half* __restrict__ A,
    const __half* __restrict__ Bt, int brow, int bcol, int kk, int tid)
{
#pragma unroll
    for (int i = 0; i < 4; i++) {
        int idx = tid + (i << 7);
        int r = idx >> 2, c8 = (idx & 3) << 3;
        const uint32_t doff = (uint32_t)(s * OPH + r * STW + c8) * 2;
        cp16(As_s + doff, A + (size_t)(brow + r) * DD + kk + c8);
        cp16(Bs_s + doff, Bt + (size_t)(bcol + r) * DD + kk + c8);
    }
    cp_commit();
}

template <typename EpiF>
__device__ __forceinline__ void gemm_run(
    char* sm, const __half* __restrict__ A, const __half* __restrict__ Bt,
    int brow, int bcol, EpiF epi)
{
    const uint32_t As_s = (uint32_t)__cvta_generic_to_shared(sm);
    const uint32_t Bs_s = As_s + 3 * OPH * 2;

    const int tid = threadIdx.x;
    const int lane = tid & 31;
    const int warp = tid >> 5;
    const int wm = warp >> 1, wn = warp & 1;

    const int arow = wm * 64 + (lane & 7) + ((lane >> 3) & 1) * 8;
    const int acolH = (lane >> 4) * 8;
    const int brw = wn * 64 + (lane & 7) + (lane >> 4) * 8;
    const int bcolH = ((lane >> 3) & 1) * 8;
    const uint32_t a_base = As_s + (uint32_t)(arow * STW + acolH) * 2;
    const uint32_t b_base = Bs_s + (uint32_t)(brw * STW + bcolH) * 2;

    float acc[4][8][4];
#pragma unroll
    for (int mi = 0; mi < 4; mi++)
#pragma unroll
        for (int ni = 0; ni < 8; ni++)
#pragma unroll
            for (int f = 0; f < 4; f++) acc[mi][ni][f] = 0.f;

    constexpr int NCH = DD / 32;
    gemm_stage(As_s, Bs_s, 0, A, Bt, brow, bcol, 0, tid);
    gemm_stage(As_s, Bs_s, 1, A, Bt, brow, bcol, 32, tid);

    for (int i = 0; i < NCH; i++) {
        if (i + 1 < NCH) cp_wait<1>(); else cp_wait<0>();
        __syncthreads();
        if (i + 2 < NCH)
            gemm_stage(As_s, Bs_s, (i + 2) % 3, A, Bt, brow, bcol,
                       (i + 2) * 32, tid);
        const uint32_t soff = (uint32_t)((i % 3) * OPH) * 2;
#pragma unroll
        for (int ks = 0; ks < 2; ks++) {
            const uint32_t ko = soff + (uint32_t)(ks * 16) * 2;
            uint32_t a[4][4], b[8][2];
#pragma unroll
            for (int mi = 0; mi < 4; mi++)
                ldsm4(a[mi][0], a[mi][1], a[mi][2], a[mi][3],
                      a_base + ko + (uint32_t)(mi * 16 * STW) * 2);
#pragma unroll
            for (int nj = 0; nj < 4; nj++)
                ldsm4(b[2 * nj][0], b[2 * nj][1],
                      b[2 * nj + 1][0], b[2 * nj + 1][1],
                      b_base + ko + (uint32_t)(nj * 16 * STW) * 2);
#pragma unroll
            for (int mi = 0; mi < 4; mi++)
#pragma unroll
                for (int ni = 0; ni < 8; ni++)
                    mma16(acc[mi][ni], a[mi], b[ni]);
        }
    }
    epi(acc, lane, wm, wn);
}

// ---------------------------------------------------------------------------
// K1: QKV GEMM + RoPE.  mat==2 (V): smem transpose -> g_vt[b,h,dh,s].
// ---------------------------------------------------------------------------
__global__ __launch_bounds__(128, 2) void qkv_mma(
    const float* __restrict__ cosT, const float* __restrict__ sinT)
{
    extern __shared__ char sm[];
    const int mat = blockIdx.z;
    const __half* __restrict__ w =
        (mat == 0) ? g_wqt : (mat == 1) ? g_wkt : g_wvt;
    const int brow = blockIdx.y * 128;
    const int bcol = blockIdx.x * 128;

    gemm_run(sm, g_xh, w, brow, bcol,
        [&](float acc[4][8][4], int lane, int wm, int wn) {
            const int tid = threadIdx.x;
            if (mat < 2) {
                __half* __restrict__ out = (mat == 0) ? g_q : g_k;
                const int ar = wm * 64 + (lane >> 2);
                const int ac = wn * 64 + (lane & 3) * 2;
#pragma unroll
                for (int mi = 0; mi < 4; mi++) {
#pragma unroll
                    for (int hp = 0; hp < 2; hp++) {
                        const int row = brow + ar + mi * 16 + hp * 8;
                        const int bb = row >> 11;
                        const int ss = row & (SS - 1);
#pragma unroll
                        for (int ni = 0; ni < 8; ni++) {
                            const int col = bcol + ac + ni * 8;
                            const int hh = col >> 6;
                            const int dh = col & (DH - 1);
                            float c0 = acc[mi][ni][hp * 2 + 0];
                            float c1 = acc[mi][ni][hp * 2 + 1];
                            const int fi = ss * 32 + (dh >> 1);
                            const float cs = cosT[fi], sn = sinT[fi];
                            const float o0 = c0 * cs - c1 * sn;
                            const float o1 = c0 * sn + c1 * cs;
                            c0 = o0; c1 = o1;
                            if (mat == 0) { c0 *= 0.125f; c1 *= 0.125f; }
                            *reinterpret_cast<__half2*>(
                                out + ((size_t)(bb * HH + hh) * SS + ss) * DH + dh) =
                                __floats2half2_rn(c0, c1);
                        }
                    }
                }
            } else {
                __syncthreads();
                __half* T = reinterpret_cast<__half*>(sm);  // [128][136]
                const int ar = wm * 64 + (lane >> 2);
                const int ac = wn * 64 + (lane & 3) * 2;
#pragma unroll
                for (int mi = 0; mi < 4; mi++)
#pragma unroll
                    for (int hp = 0; hp < 2; hp++) {
                        const int rl = ar + mi * 16 + hp * 8;
#pragma unroll
                        for (int ni = 0; ni < 8; ni++) {
                            const int cl = ac + ni * 8;
                            T[(cl)     * 136 + rl] =
                                __float2half_rn(acc[mi][ni][hp * 2]);
                            T[(cl + 1) * 136 + rl] =
                                __float2half_rn(acc[mi][ni][hp * 2 + 1]);
                        }
                    }
                __syncthreads();
                const int bb = brow >> 11;
                const int srow = brow & (SS - 1);
#pragma unroll
                for (int i = 0; i < 16; i++) {
                    int idx = tid + (i << 7);
                    int r = idx >> 4, c8 = (idx & 15) << 3;
                    const int dhg = bcol + r;
                    const int hh = dhg >> 6, dh = dhg & 63;
                    uint4 v = *reinterpret_cast<const uint4*>(&T[r * 136 + c8]);
                    *reinterpret_cast<uint4*>(
                        g_vt + ((size_t)(bb * HH + hh) * DH + dh) * SS +
                        srow + c8) = v;
                }
            }
        });
}

// ---------------------------------------------------------------------------
// K3: output projection (half in, fp32 out)
// ---------------------------------------------------------------------------
__global__ __launch_bounds__(128, 2) void proj_mma(float* __restrict__ Cout)
{
    extern __shared__ char sm[];
    const int brow = blockIdx.y * 128;
    const int bcol = blockIdx.x * 128;

    gemm_run(sm, g_att, g_wot, brow, bcol,
        [&](float acc[4][8][4], int lane, int wm, int wn) {
            const int ar = wm * 64 + (lane >> 2);
            const int ac = wn * 64 + (lane & 3) * 2;
#pragma unroll
            for (int mi = 0; mi < 4; mi++)
#pragma unroll
                for (int hp = 0; hp < 2; hp++) {
                    const int row = brow + ar + mi * 16 + hp * 8;
#pragma unroll
                    for (int ni = 0; ni < 8; ni++) {
                        const int col = bcol + ac + ni * 8;
                        *reinterpret_cast<float2*>(
                            Cout + (size_t)row * DD + col) =
                            make_float2(acc[mi][ni][hp * 2],
                                        acc[mi][ni][hp * 2 + 1]);
                    }
                }
        });
}

// ---------------------------------------------------------------------------
// K2: flash attention — 128 q-rows/block, 4 warps (m32n64), 2 blocks/SM.
// Vs: 80 rows (64 data + ones row 64 + zeros). l via PV ones-column.
// smem: Qs[128][72] + Ks[2][64][72] + Vs[2][80][72] + Ps[128][72] = 78336 B.
// ---------------------------------------------------------------------------
constexpr int AST = 72;                     // halves
constexpr int QS_H = 128 * AST;             // 9216
constexpr int KS_H = 64 * AST;              // 4608
constexpr int VS_H = 80 * AST;              // 5760
constexpr int ATT_SMEM = (2 * QS_H + 2 * KS_H + 2 * VS_H) * 2;  // 78336 B

__device__ __forceinline__ void attn_stage_kv(
    uint32_t Ks_s, uint32_t Vs_s, int s,
    const __half* __restrict__ K, const __half* __restrict__ Vt,
    int kt, int tid)
{
#pragma unroll
    for (int i = 0; i < 4; i++) {
        int idx = tid + (i << 7);
        int r = idx >> 3, c8 = (idx & 7) << 3;
        cp16(Ks_s + (uint32_t)(s * KS_H + r * AST + c8) * 2,
             K + (size_t)(kt * 64 + r) * DH + c8);
        cp16(Vs_s + (uint32_t)(s * VS_H + r * AST + c8) * 2,
             Vt + (size_t)r * SS + kt * 64 + c8);
    }
    cp_commit();
}

__global__ __launch_bounds__(128, 2) void attn_mma()
{
    extern __shared__ char smc[];
    __half* Qs = reinterpret_cast<__half*>(smc);
    __half* Ks = Qs + QS_H;
    __half* Vs = Ks + 2 * KS_H;
    __half* Ps = Vs + 2 * VS_H;
    const uint32_t Qs_s = (uint32_t)__cvta_generic_to_shared(Qs);
    const uint32_t Ks_s = (uint32_t)__cvta_generic_to_shared(Ks);
    const uint32_t Vs_s = (uint32_t)__cvta_generic_to_shared(Vs);
    const uint32_t Ps_s = (uint32_t)__cvta_generic_to_shared(Ps);

    const int qt = blockIdx.x, h = blockIdx.y, b = blockIdx.z;
    const __half* __restrict__ Q  = g_q  + ((size_t)(b * HH + h) * SS + qt * 128) * DH;
    const __half* __restrict__ K  = g_k  + (size_t)(b * HH + h) * SS * DH;
    const __half* __restrict__ Vt = g_vt + (size_t)(b * HH + h) * DH * SS;

    const int tid = threadIdx.x;
    const int lane = tid & 31;
    const int warp = tid >> 5;     // 0..3
    const int qbase = warp * 32;

    // prologue: KV0, Q, KV1; ones/zeros rows of Vs (both stages)
    attn_stage_kv(Ks_s, Vs_s, 0, K, Vt, 0, tid);
#pragma unroll
    for (int i = 0; i < 8; i++) {
        int idx = tid + (i << 7);
        int r = idx >> 3, c8 = (idx & 7) << 3;
        cp16(Qs_s + (uint32_t)(r * AST + c8) * 2, Q + (size_t)r * DH + c8);
    }
    cp_commit();
    attn_stage_kv(Ks_s, Vs_s, 1, K, Vt, 1, tid);

    for (int idx = tid; idx < 2 * 16 * AST; idx += 128) {
        const int s = idx / (16 * AST);
        const int rem = idx % (16 * AST);
        const int r = 64 + rem / AST;
        const int c = rem % AST;
        Vs[s * VS_H + r * AST + c] =
            (r == 64) ? __float2half(1.f) : __float2half(0.f);
    }

    // ldmatrix lane bases (bytes)
    const int arow = (lane & 7) + ((lane >> 3) & 1) * 8;
    const int acolH = (lane >> 4) * 8;
    const int brw = (lane & 7) + (lane >> 4) * 8;
    const int bcolH = ((lane >> 3) & 1) * 8;
    const uint32_t qa = Qs_s + (uint32_t)((qbase + arow) * AST + acolH) * 2;
    const uint32_t pa = Ps_s + (uint32_t)((qbase + arow) * AST + acolH) * 2;
    const uint32_t kb = Ks_s + (uint32_t)(brw * AST + bcolH) * 2;
    const uint32_t vb = Vs_s + (uint32_t)(brw * AST + bcolH) * 2;

    constexpr float L2E = 1.4426950408889634f;

    float mrow[2][2];
    float o[2][9][4];   // ni=8 is the row-sum (l) column
#pragma unroll
    for (int mi = 0; mi < 2; mi++) {
#pragma unroll
        for (int hp = 0; hp < 2; hp++) mrow[mi][hp] = -1e30f;
#pragma unroll
        for (int ni = 0; ni < 9; ni++)
#pragma unroll
            for (int f = 0; f < 4; f++) o[mi][ni][f] = 0.f;
    }

    constexpr int NKT = SS / 64;  // 32

    for (int kt = 0; kt < NKT; kt++) {
        if (kt + 1 < NKT) cp_wait<1>(); else cp_wait<0>();
        __syncthreads();

        const int s = kt & 1;
        const uint32_t kOff = (uint32_t)(s * KS_H) * 2;
        const uint32_t vOff = (uint32_t)(s * VS_H) * 2;

        // ---- S = Q @ K^T ----
        float sacc[2][8][4];
#pragma unroll
        for (int mi = 0; mi < 2; mi++)
#pragma unroll
            for (int ni = 0; ni < 8; ni++)
#pragma unroll
                for (int f = 0; f < 4; f++) sacc[mi][ni][f] = 0.f;

#pragma unroll
        for (int ks = 0; ks < 4; ks++) {
            const uint32_t ko = (uint32_t)(ks * 16) * 2;
            uint32_t a[2][4], bf[8][2];
#pragma unroll
            for (int mi = 0; mi < 2; mi++)
                ldsm4(a[mi][0], a[mi][1], a[mi][2], a[mi][3],
                      qa + ko + (uint32_t)(mi * 16 * AST) * 2);
#pragma unroll
            for (int nj = 0; nj < 4; nj++)
                ldsm4(bf[2 * nj][0], bf[2 * nj][1],
                      bf[2 * nj + 1][0], bf[2 * nj + 1][1],
                      kb + kOff + ko + (uint32_t)(nj * 16 * AST) * 2);
#pragma unroll
            for (int mi = 0; mi < 2; mi++)
#pragma unroll
                for (int ni = 0; ni < 8; ni++)
                    mma16(sacc[mi][ni], a[mi], bf[ni]);
        }

        // ---- online softmax -> Ps (half2 ex2; sums via PV ones-column) ----
#pragma unroll
        for (int mi = 0; mi < 2; mi++) {
#pragma unroll
            for (int hp = 0; hp < 2; hp++) {
                float mx = -1e30f;
#pragma unroll
                for (int ni = 0; ni < 8; ni++)
                    mx = fmaxf(mx, fmaxf(sacc[mi][ni][hp * 2],
                                         sacc[mi][ni][hp * 2 + 1]));
                mx = fmaxf(mx, __shfl_xor_sync(0xffffffffu, mx, 1));
                mx = fmaxf(mx, __shfl_xor_sync(0xffffffffu, mx, 2));
                const float mnew = fmaxf(mrow[mi][hp], mx);
                const float corr = __expf(mrow[mi][hp] - mnew);
                mrow[mi][hp] = mnew;
                const float mL2 = mnew * L2E;
                const int prow = qbase + mi * 16 + hp * 8 + (lane >> 2);
#pragma unroll
                for (int ni = 0; ni < 8; ni++) {
                    const float b0 = fmaf(sacc[mi][ni][hp * 2],     L2E, -mL2);
                    const float b1 = fmaf(sacc[mi][ni][hp * 2 + 1], L2E, -mL2);
                    const uint32_t pp = h2exp2(h2u(__floats2half2_rn(b0, b1)));
                    *reinterpret_cast<uint32_t*>(
                        &Ps[prow * AST + ni * 8 + 2 * (lane & 3)]) = pp;
                }
#pragma unroll
                for (int ni = 0; ni < 9; ni++) {
                    o[mi][ni][hp * 2]     *= corr;
                    o[mi][ni][hp * 2 + 1] *= corr;
                }
            }
        }
        __syncwarp();

        // ---- O += P @ [V^T ; ones] ----
#pragma unroll
        for (int ks = 0; ks < 4; ks++) {
            const uint32_t ko = (uint32_t)(ks * 16) * 2;
            uint32_t a[2][4], bf[10][2];
#pragma unroll
            for (int mi = 0; mi < 2; mi++)
                ldsm4(a[mi][0], a[mi][1], a[mi][2], a[mi][3],
                      pa + ko + (uint32_t)(mi * 16 * AST) * 2);
#pragma unroll
            for (int nj = 0; nj < 5; nj++)
                ldsm4(bf[2 * nj][0], bf[2 * nj][1],
                      bf[2 * nj + 1][0], bf[2 * nj + 1][1],
                      vb + vOff + ko + (uint32_t)(nj * 16 * AST) * 2);
#pragma unroll
            for (int mi = 0; mi < 2; mi++)
#pragma unroll
                for (int ni = 0; ni < 9; ni++)
                    mma16(o[mi][ni], a[mi], bf[ni]);
        }

        if (kt + 2 < NKT) {
            __syncthreads();
            attn_stage_kv(Ks_s, Vs_s, s, K, Vt, kt + 2, tid);
        }
    }

    // epilogue: l from ones-column (quad lane 0), normalize, write half
#pragma unroll
    for (int mi = 0; mi < 2; mi++)
#pragma unroll
        for (int hp = 0; hp < 2; hp++) {
            const float l = __shfl_sync(0xffffffffu, o[mi][8][hp * 2],
                                        lane & ~3);
            const float inv = 1.f / l;
            const int row = qt * 128 + qbase + mi * 16 + hp * 8 + (lane >> 2);
#pragma unroll
            for (int ni = 0; ni < 8; ni++) {
                const int col = h * 64 + ni * 8 + (lane & 3) * 2;
                *reinterpret_cast<__half2*>(
                    g_att + (size_t)(b * SS + row) * DD + col) =
                    __floats2half2_rn(o[mi][ni][hp * 2] * inv,
                                      o[mi][ni][hp * 2 + 1] * inv);
            }
        }
}

// ---------------------------------------------------------------------------
extern "C" void kernel_launch(void* const* d_in, const int* in_sizes, int n_in,
                              void* d_out, int out_size)
{
    const float* x    = (const float*)d_in[0];
    const float* cosT = (const float*)d_in[1];
    const float* sinT = (const float*)d_in[2];
    const float* wq   = (const float*)d_in[3];
    const float* wk   = (const float*)d_in[4];
    const float* wv   = (const float*)d_in[5];
    const float* wo   = (const float*)d_in[6];
    float* out = (float*)d_out;

    static bool attr_set = false;
    if (!attr_set) {
        cudaFuncSetAttribute(qkv_mma,
                             cudaFuncAttributeMaxDynamicSharedMemorySize, GEMM_SMEM);
        cudaFuncSetAttribute(proj_mma,
                             cudaFuncAttributeMaxDynamicSharedMemorySize, GEMM_SMEM);
        cudaFuncSetAttribute(attn_mma,
                             cudaFuncAttributeMaxDynamicSharedMemorySize, ATT_SMEM);
        attr_set = true;
    }

    cvt_xh<<<256, 256>>>(x);
    cvt_wT<<<dim3(32, 32, 4), dim3(32, 8)>>>(wq, wk, wv, wo);
    qkv_mma<<<dim3(DD / 128, MT / 128, 3), 128, GEMM_SMEM>>>(cosT, sinT);
    attn_mma<<<dim3(SS / 128, HH, BB), 128, ATT_SMEM>>>();
    proj_mma<<<dim3(DD / 128, MT / 128, 1), 128, GEMM_SMEM>>>(out);
}

// round 14
// speedup vs baseline: 2.0094x; 1.0062x over previous
#include <cuda_runtime.h>
#include <cuda_fp16.h>
#include <cstdint>

// ---------------------------------------------------------------------------
// MultiHeadAttention B=2,S=2048,D=1024,H=16,Dh=64 fp32 — R14:
//  R13 + attention KV ring deepened to 3 stages, single __syncthreads/iter
//  (GEMM-style wait -> sync -> stage(kt+2) -> compute loop).
// ---------------------------------------------------------------------------

constexpr int BB = 2;
constexpr int SS = 2048;
constexpr int DD = 1024;
constexpr int HH = 16;
constexpr int DH = 64;
constexpr int MT = BB * SS;   // 4096

__device__ __half g_q[BB * HH * SS * DH];
__device__ __half g_k[BB * HH * SS * DH];
__device__ __half g_vt[BB * HH * DH * SS];   // V^T: [b,h,dh,s]
__device__ __half g_att[MT * DD];
__device__ __half g_xh[MT * DD];
__device__ __half g_wqt[DD * DD];            // weights transposed [n][k]
__device__ __half g_wkt[DD * DD];
__device__ __half g_wvt[DD * DD];
__device__ __half g_wot[DD * DD];

__device__ __forceinline__ uint32_t h2u(__half2 h) {
    return *reinterpret_cast<uint32_t*>(&h);
}
__device__ __forceinline__ uint32_t h2exp2(uint32_t x) {
    uint32_t r;
    asm("ex2.approx.f16x2 %0, %1;" : "=r"(r) : "r"(x));
    return r;
}
__device__ __forceinline__ void mma16(float* d, const uint32_t* a,
                                      const uint32_t* b) {
    asm volatile(
        "mma.sync.aligned.m16n8k16.row.col.f32.f16.f16.f32 "
        "{%0,%1,%2,%3}, {%4,%5,%6,%7}, {%8,%9}, {%0,%1,%2,%3};"
        : "+f"(d[0]), "+f"(d[1]), "+f"(d[2]), "+f"(d[3])
        : "r"(a[0]), "r"(a[1]), "r"(a[2]), "r"(a[3]), "r"(b[0]), "r"(b[1]));
}
__device__ __forceinline__ void ldsm4(uint32_t& r0, uint32_t& r1,
                                      uint32_t& r2, uint32_t& r3,
                                      uint32_t addr) {
    asm volatile(
        "ldmatrix.sync.aligned.m8n8.x4.shared.b16 {%0,%1,%2,%3}, [%4];"
        : "=r"(r0), "=r"(r1), "=r"(r2), "=r"(r3) : "r"(addr));
}
__device__ __forceinline__ void cp16(uint32_t dst, const void* src) {
    asm volatile("cp.async.cg.shared.global [%0], [%1], 16;"
                 :: "r"(dst), "l"(src));
}
__device__ __forceinline__ void cp_commit() {
    asm volatile("cp.async.commit_group;");
}
template <int N>
__device__ __forceinline__ void cp_wait() {
    asm volatile("cp.async.wait_group %0;" :: "n"(N));
}

// ---------------------------------------------------------------------------
// K0a: x -> half.  K0b: weights -> half, transposed [n][k].
// ---------------------------------------------------------------------------
__global__ __launch_bounds__(256) void cvt_xh(const float* __restrict__ x) {
    const int n4 = (MT * DD) >> 2;
    const float4* s4 = reinterpret_cast<const float4*>(x);
    uint2* d4 = reinterpret_cast<uint2*>(g_xh);
    for (int i = blockIdx.x * 256 + threadIdx.x; i < n4; i += gridDim.x * 256) {
        float4 v = s4[i];
        uint2 o;
        o.x = h2u(__floats2half2_rn(v.x, v.y));
        o.y = h2u(__floats2half2_rn(v.z, v.w));
        d4[i] = o;
    }
}

__global__ void cvt_wT(
    const float* __restrict__ wq, const float* __restrict__ wk,
    const float* __restrict__ wv, const float* __restrict__ wo) {
    __shared__ float t[32][33];
    const int z = blockIdx.z;
    const float* src = (z == 0) ? wq : (z == 1) ? wk : (z == 2) ? wv : wo;
    __half* dst = (z == 0) ? g_wqt : (z == 1) ? g_wkt : (z == 2) ? g_wvt : g_wot;
    const int tx = threadIdx.x, ty = threadIdx.y;
    const int kb = blockIdx.y * 32, nb = blockIdx.x * 32;
#pragma unroll
    for (int i = 0; i < 4; i++) {
        int k = kb + ty + i * 8;
        t[ty + i * 8][tx] = src[(size_t)k * DD + nb + tx];
    }
    __syncthreads();
#pragma unroll
    for (int i = 0; i < 4; i++) {
        int n = nb + ty + i * 8;
        dst[(size_t)n * DD + kb + tx] = __float2half_rn(t[tx][ty + i * 8]);
    }
}

// ---------------------------------------------------------------------------
// GEMM (R11): 128x128 tile, BK=32 halves, 4 warps, 64x64/warp, 3-stage.
// ---------------------------------------------------------------------------
constexpr int STW = 40;
constexpr int OPH = 128 * STW;
constexpr int GEMM_SMEM = 3 * 2 * OPH * 2;

__device__ __forceinline__ void gemm_stage(
    uint32_t As_s, uint32_t Bs_s, int s, const __half* __restrict__ A,
    const __half* __restrict__ Bt, int brow, int bcol, int kk, int tid)
{
#pragma unroll
    for (int i = 0; i < 4; i++) {
        int idx = tid + (i << 7);
        int r = idx >> 2, c8 = (idx & 3) << 3;
        const uint32_t doff = (uint32_t)(s * OPH + r * STW + c8) * 2;
        cp16(As_s + doff, A + (size_t)(brow + r) * DD + kk + c8);
        cp16(Bs_s + doff, Bt + (size_t)(bcol + r) * DD + kk + c8);
    }
    cp_commit();
}

template <typename EpiF>
__device__ __forceinline__ void gemm_run(
    char* sm, const __half* __restrict__ A, const __half* __restrict__ Bt,
    int brow, int bcol, EpiF epi)
{
    const uint32_t As_s = (uint32_t)__cvta_generic_to_shared(sm);
    const uint32_t Bs_s = As_s + 3 * OPH * 2;

    const int tid = threadIdx.x;
    const int lane = tid & 31;
    const int warp = tid >> 5;
    const int wm = warp >> 1, wn = warp & 1;

    const int arow = wm * 64 + (lane & 7) + ((lane >> 3) & 1) * 8;
    const int acolH = (lane >> 4) * 8;
    const int brw = wn * 64 + (lane & 7) + (lane >> 4) * 8;
    const int bcolH = ((lane >> 3) & 1) * 8;
    const uint32_t a_base = As_s + (uint32_t)(arow * STW + acolH) * 2;
    const uint32_t b_base = Bs_s + (uint32_t)(brw * STW + bcolH) * 2;

    float acc[4][8][4];
#pragma unroll
    for (int mi = 0; mi < 4; mi++)
#pragma unroll
        for (int ni = 0; ni < 8; ni++)
#pragma unroll
            for (int f = 0; f < 4; f++) acc[mi][ni][f] = 0.f;

    constexpr int NCH = DD / 32;
    gemm_stage(As_s, Bs_s, 0, A, Bt, brow, bcol, 0, tid);
    gemm_stage(As_s, Bs_s, 1, A, Bt, brow, bcol, 32, tid);

    for (int i = 0; i < NCH; i++) {
        if (i + 1 < NCH) cp_wait<1>(); else cp_wait<0>();
        __syncthreads();
        if (i + 2 < NCH)
            gemm_stage(As_s, Bs_s, (i + 2) % 3, A, Bt, brow, bcol,
                       (i + 2) * 32, tid);
        const uint32_t soff = (uint32_t)((i % 3) * OPH) * 2;
#pragma unroll
        for (int ks = 0; ks < 2; ks++) {
            const uint32_t ko = soff + (uint32_t)(ks * 16) * 2;
            uint32_t a[4][4], b[8][2];
#pragma unroll
            for (int mi = 0; mi < 4; mi++)
                ldsm4(a[mi][0], a[mi][1], a[mi][2], a[mi][3],
                      a_base + ko + (uint32_t)(mi * 16 * STW) * 2);
#pragma unroll
            for (int nj = 0; nj < 4; nj++)
                ldsm4(b[2 * nj][0], b[2 * nj][1],
                      b[2 * nj + 1][0], b[2 * nj + 1][1],
                      b_base + ko + (uint32_t)(nj * 16 * STW) * 2);
#pragma unroll
            for (int mi = 0; mi < 4; mi++)
#pragma unroll
                for (int ni = 0; ni < 8; ni++)
                    mma16(acc[mi][ni], a[mi], b[ni]);
        }
    }
    epi(acc, lane, wm, wn);
}

// ---------------------------------------------------------------------------
// K1: QKV GEMM + RoPE.  mat==2 (V): smem transpose -> g_vt[b,h,dh,s].
// ---------------------------------------------------------------------------
__global__ __launch_bounds__(128, 2) void qkv_mma(
    const float* __restrict__ cosT, const float* __restrict__ sinT)
{
    extern __shared__ char sm[];
    const int mat = blockIdx.z;
    const __half* __restrict__ w =
        (mat == 0) ? g_wqt : (mat == 1) ? g_wkt : g_wvt;
    const int brow = blockIdx.y * 128;
    const int bcol = blockIdx.x * 128;

    gemm_run(sm, g_xh, w, brow, bcol,
        [&](float acc[4][8][4], int lane, int wm, int wn) {
            const int tid = threadIdx.x;
            if (mat < 2) {
                __half* __restrict__ out = (mat == 0) ? g_q : g_k;
                const int ar = wm * 64 + (lane >> 2);
                const int ac = wn * 64 + (lane & 3) * 2;
#pragma unroll
                for (int mi = 0; mi < 4; mi++) {
#pragma unroll
                    for (int hp = 0; hp < 2; hp++) {
                        const int row = brow + ar + mi * 16 + hp * 8;
                        const int bb = row >> 11;
                        const int ss = row & (SS - 1);
#pragma unroll
                        for (int ni = 0; ni < 8; ni++) {
                            const int col = bcol + ac + ni * 8;
                            const int hh = col >> 6;
                            const int dh = col & (DH - 1);
                            float c0 = acc[mi][ni][hp * 2 + 0];
                            float c1 = acc[mi][ni][hp * 2 + 1];
                            const int fi = ss * 32 + (dh >> 1);
                            const float cs = cosT[fi], sn = sinT[fi];
                            const float o0 = c0 * cs - c1 * sn;
                            const float o1 = c0 * sn + c1 * cs;
                            c0 = o0; c1 = o1;
                            if (mat == 0) { c0 *= 0.125f; c1 *= 0.125f; }
                            *reinterpret_cast<__half2*>(
                                out + ((size_t)(bb * HH + hh) * SS + ss) * DH + dh) =
                                __floats2half2_rn(c0, c1);
                        }
                    }
                }
            } else {
                __syncthreads();
                __half* T = reinterpret_cast<__half*>(sm);  // [128][136]
                const int ar = wm * 64 + (lane >> 2);
                const int ac = wn * 64 + (lane & 3) * 2;
#pragma unroll
                for (int mi = 0; mi < 4; mi++)
#pragma unroll
                    for (int hp = 0; hp < 2; hp++) {
                        const int rl = ar + mi * 16 + hp * 8;
#pragma unroll
                        for (int ni = 0; ni < 8; ni++) {
                            const int cl = ac + ni * 8;
                            T[(cl)     * 136 + rl] =
                                __float2half_rn(acc[mi][ni][hp * 2]);
                            T[(cl + 1) * 136 + rl] =
                                __float2half_rn(acc[mi][ni][hp * 2 + 1]);
                        }
                    }
                __syncthreads();
                const int bb = brow >> 11;
                const int srow = brow & (SS - 1);
#pragma unroll
                for (int i = 0; i < 16; i++) {
                    int idx = tid + (i << 7);
                    int r = idx >> 4, c8 = (idx & 15) << 3;
                    const int dhg = bcol + r;
                    const int hh = dhg >> 6, dh = dhg & 63;
                    uint4 v = *reinterpret_cast<const uint4*>(&T[r * 136 + c8]);
                    *reinterpret_cast<uint4*>(
                        g_vt + ((size_t)(bb * HH + hh) * DH + dh) * SS +
                        srow + c8) = v;
                }
            }
        });
}

// ---------------------------------------------------------------------------
// K3: output projection (half in, fp32 out)
// ---------------------------------------------------------------------------
__global__ __launch_bounds__(128, 2) void proj_mma(float* __restrict__ Cout)
{
    extern __shared__ char sm[];
    const int brow = blockIdx.y * 128;
    const int bcol = blockIdx.x * 128;

    gemm_run(sm, g_att, g_wot, brow, bcol,
        [&](float acc[4][8][4], int lane, int wm, int wn) {
            const int ar = wm * 64 + (lane >> 2);
            const int ac = wn * 64 + (lane & 3) * 2;
#pragma unroll
            for (int mi = 0; mi < 4; mi++)
#pragma unroll
                for (int hp = 0; hp < 2; hp++) {
                    const int row = brow + ar + mi * 16 + hp * 8;
#pragma unroll
                    for (int ni = 0; ni < 8; ni++) {
                        const int col = bcol + ac + ni * 8;
                        *reinterpret_cast<float2*>(
                            Cout + (size_t)row * DD + col) =
                            make_float2(acc[mi][ni][hp * 2],
                                        acc[mi][ni][hp * 2 + 1]);
                    }
                }
        });
}

// ---------------------------------------------------------------------------
// K2: flash attention — 128 q-rows/block, 4 warps (m32n64), 2 blocks/SM,
// 3-stage KV ring, single __syncthreads per iteration.
// Vs: 80 rows (64 data + ones row 64 + zeros). l via PV ones-column.
// smem: Qs[128][72] + Ks[3][64][72] + Vs[3][80][72] + Ps[128][72] = 99072 B.
// ---------------------------------------------------------------------------
constexpr int AST = 72;                     // halves
constexpr int QS_H = 128 * AST;             // 9216
constexpr int KS_H = 64 * AST;              // 4608
constexpr int VS_H = 80 * AST;              // 5760
constexpr int ATT_SMEM = (2 * QS_H + 3 * KS_H + 3 * VS_H) * 2;  // 99072 B

__device__ __forceinline__ void attn_stage_kv(
    uint32_t Ks_s, uint32_t Vs_s, int s,
    const __half* __restrict__ K, const __half* __restrict__ Vt,
    int kt, int tid)
{
#pragma unroll
    for (int i = 0; i < 4; i++) {
        int idx = tid + (i << 7);
        int r = idx >> 3, c8 = (idx & 7) << 3;
        cp16(Ks_s + (uint32_t)(s * KS_H + r * AST + c8) * 2,
             K + (size_t)(kt * 64 + r) * DH + c8);
        cp16(Vs_s + (uint32_t)(s * VS_H + r * AST + c8) * 2,
             Vt + (size_t)r * SS + kt * 64 + c8);
    }
    cp_commit();
}

__global__ __launch_bounds__(128, 2) void attn_mma()
{
    extern __shared__ char smc[];
    __half* Qs = reinterpret_cast<__half*>(smc);
    __half* Ks = Qs + QS_H;
    __half* Vs = Ks + 3 * KS_H;
    __half* Ps = Vs + 3 * VS_H;
    const uint32_t Qs_s = (uint32_t)__cvta_generic_to_shared(Qs);
    const uint32_t Ks_s = (uint32_t)__cvta_generic_to_shared(Ks);
    const uint32_t Vs_s = (uint32_t)__cvta_generic_to_shared(Vs);
    const uint32_t Ps_s = (uint32_t)__cvta_generic_to_shared(Ps);

    const int qt = blockIdx.x, h = blockIdx.y, b = blockIdx.z;
    const __half* __restrict__ Q  = g_q  + ((size_t)(b * HH + h) * SS + qt * 128) * DH;
    const __half* __restrict__ K  = g_k  + (size_t)(b * HH + h) * SS * DH;
    const __half* __restrict__ Vt = g_vt + (size_t)(b * HH + h) * DH * SS;

    const int tid = threadIdx.x;
    const int lane = tid & 31;
    const int warp = tid >> 5;     // 0..3
    const int qbase = warp * 32;

    // ones/zeros rows of Vs (rows 64..79, all 3 slots) — plain STS, rows
    // disjoint from cp.async targets (rows 0..63).
    for (int idx = tid; idx < 3 * 16 * AST; idx += 128) {
        const int s = idx / (16 * AST);
        const int rem = idx % (16 * AST);
        const int r = 64 + rem / AST;
        const int c = rem % AST;
        Vs[s * VS_H + r * AST + c] =
            (r == 64) ? __float2half(1.f) : __float2half(0.f);
    }

    // prologue: Q + KV0 committed together (g0), then KV1 (g1).
#pragma unroll
    for (int i = 0; i < 8; i++) {
        int idx = tid + (i << 7);
        int r = idx >> 3, c8 = (idx & 7) << 3;
        cp16(Qs_s + (uint32_t)(r * AST + c8) * 2, Q + (size_t)r * DH + c8);
    }
    attn_stage_kv(Ks_s, Vs_s, 0, K, Vt, 0, tid);   // commits Q + KV0
    attn_stage_kv(Ks_s, Vs_s, 1, K, Vt, 1, tid);   // g1

    // ldmatrix lane bases (bytes)
    const int arow = (lane & 7) + ((lane >> 3) & 1) * 8;
    const int acolH = (lane >> 4) * 8;
    const int brw = (lane & 7) + (lane >> 4) * 8;
    const int bcolH = ((lane >> 3) & 1) * 8;
    const uint32_t qa = Qs_s + (uint32_t)((qbase + arow) * AST + acolH) * 2;
    const uint32_t pa = Ps_s + (uint32_t)((qbase + arow) * AST + acolH) * 2;
    const uint32_t kb = Ks_s + (uint32_t)(brw * AST + bcolH) * 2;
    const uint32_t vb = Vs_s + (uint32_t)(brw * AST + bcolH) * 2;

    constexpr float L2E = 1.4426950408889634f;

    float mrow[2][2];
    float o[2][9][4];   // ni=8 is the row-sum (l) column
#pragma unroll
    for (int mi = 0; mi < 2; mi++) {
#pragma unroll
        for (int hp = 0; hp < 2; hp++) mrow[mi][hp] = -1e30f;
#pragma unroll
        for (int ni = 0; ni < 9; ni++)
#pragma unroll
            for (int f = 0; f < 4; f++) o[mi][ni][f] = 0.f;
    }

    constexpr int NKT = SS / 64;  // 32

    for (int kt = 0; kt < NKT; kt++) {
        if (kt + 1 < NKT) cp_wait<1>(); else cp_wait<0>();
        __syncthreads();
        if (kt + 2 < NKT)
            attn_stage_kv(Ks_s, Vs_s, (kt + 2) % 3, K, Vt, kt + 2, tid);

        const int s = kt % 3;
        const uint32_t kOff = (uint32_t)(s * KS_H) * 2;
        const uint32_t vOff = (uint32_t)(s * VS_H) * 2;

        // ---- S = Q @ K^T ----
        float sacc[2][8][4];
#pragma unroll
        for (int mi = 0; mi < 2; mi++)
#pragma unroll
            for (int ni = 0; ni < 8; ni++)
#pragma unroll
                for (int f = 0; f < 4; f++) sacc[mi][ni][f] = 0.f;

#pragma unroll
        for (int ks = 0; ks < 4; ks++) {
            const uint32_t ko = (uint32_t)(ks * 16) * 2;
            uint32_t a[2][4], bf[8][2];
#pragma unroll
            for (int mi = 0; mi < 2; mi++)
                ldsm4(a[mi][0], a[mi][1], a[mi][2], a[mi][3],
                      qa + ko + (uint32_t)(mi * 16 * AST) * 2);
#pragma unroll
            for (int nj = 0; nj < 4; nj++)
                ldsm4(bf[2 * nj][0], bf[2 * nj][1],
                      bf[2 * nj + 1][0], bf[2 * nj + 1][1],
                      kb + kOff + ko + (uint32_t)(nj * 16 * AST) * 2);
#pragma unroll
            for (int mi = 0; mi < 2; mi++)
#pragma unroll
                for (int ni = 0; ni < 8; ni++)
                    mma16(sacc[mi][ni], a[mi], bf[ni]);
        }

        // ---- online softmax -> Ps (half2 ex2; sums via PV ones-column) ----
#pragma unroll
        for (int mi = 0; mi < 2; mi++) {
#pragma unroll
            for (int hp = 0; hp < 2; hp++) {
                float mx = -1e30f;
#pragma unroll
                for (int ni = 0; ni < 8; ni++)
                    mx = fmaxf(mx, fmaxf(sacc[mi][ni][hp * 2],
                                         sacc[mi][ni][hp * 2 + 1]));
                mx = fmaxf(mx, __shfl_xor_sync(0xffffffffu, mx, 1));
                mx = fmaxf(mx, __shfl_xor_sync(0xffffffffu, mx, 2));
                const float mnew = fmaxf(mrow[mi][hp], mx);
                const float corr = __expf(mrow[mi][hp] - mnew);
                mrow[mi][hp] = mnew;
                const float mL2 = mnew * L2E;
                const int prow = qbase + mi * 16 + hp * 8 + (lane >> 2);
#pragma unroll
                for (int ni = 0; ni < 8; ni++) {
                    const float b0 = fmaf(sacc[mi][ni][hp * 2],     L2E, -mL2);
                    const float b1 = fmaf(sacc[mi][ni][hp * 2 + 1], L2E, -mL2);
                    const uint32_t pp = h2exp2(h2u(__floats2half2_rn(b0, b1)));
                    *reinterpret_cast<uint32_t*>(
                        &Ps[prow * AST + ni * 8 + 2 * (lane & 3)]) = pp;
                }
#pragma unroll
                for (int ni = 0; ni < 9; ni++) {
                    o[mi][ni][hp * 2]     *= corr;
                    o[mi][ni][hp * 2 + 1] *= corr;
                }
            }
        }
        __syncwarp();

        // ---- O += P @ [V^T ; ones] ----
#pragma unroll
        for (int ks = 0; ks < 4; ks++) {
            const uint32_t ko = (uint32_t)(ks * 16) * 2;
            uint32_t a[2][4], bf[10][2];
#pragma unroll
            for (int mi = 0; mi < 2; mi++)
                ldsm4(a[mi][0], a[mi][1], a[mi][2], a[mi][3],
                      pa + ko + (uint32_t)(mi * 16 * AST) * 2);
#pragma unroll
            for (int nj = 0; nj < 5; nj++)
                ldsm4(bf[2 * nj][0], bf[2 * nj][1],
                      bf[2 * nj + 1][0], bf[2 * nj + 1][1],
                      vb + vOff + ko + (uint32_t)(nj * 16 * AST) * 2);
#pragma unroll
            for (int mi = 0; mi < 2; mi++)
#pragma unroll
                for (int ni = 0; ni < 9; ni++)
                    mma16(o[mi][ni], a[mi], bf[ni]);
        }
    }

    // epilogue: l from ones-column (quad lane 0), normalize, write half
#pragma unroll
    for (int mi = 0; mi < 2; mi++)
#pragma unroll
        for (int hp = 0; hp < 2; hp++) {
            const float l = __shfl_sync(0xffffffffu, o[mi][8][hp * 2],
                                        lane & ~3);
            const float inv = 1.f / l;
            const int row = qt * 128 + qbase + mi * 16 + hp * 8 + (lane >> 2);
#pragma unroll
            for (int ni = 0; ni < 8; ni++) {
                const int col = h * 64 + ni * 8 + (lane & 3) * 2;
                *reinterpret_cast<__half2*>(
                    g_att + (size_t)(b * SS + row) * DD + col) =
                    __floats2half2_rn(o[mi][ni][hp * 2] * inv,
                                      o[mi][ni][hp * 2 + 1] * inv);
            }
        }
}

// ---------------------------------------------------------------------------
extern "C" void kernel_launch(void* const* d_in, const int* in_sizes, int n_in,
                              void* d_out, int out_size)
{
    const float* x    = (const float*)d_in[0];
    const float* cosT = (const float*)d_in[1];
    const float* sinT = (const float*)d_in[2];
    const float* wq   = (const float*)d_in[3];
    const float* wk   = (const float*)d_in[4];
    const float* wv   = (const float*)d_in[5];
    const float* wo   = (const float*)d_in[6];
    float* out = (float*)d_out;

    static bool attr_set = false;
    if (!attr_set) {
        cudaFuncSetAttribute(qkv_mma,
                             cudaFuncAttributeMaxDynamicSharedMemorySize, GEMM_SMEM);
        cudaFuncSetAttribute(proj_mma,
                             cudaFuncAttributeMaxDynamicSharedMemorySize, GEMM_SMEM);
        cudaFuncSetAttribute(attn_mma,
                             cudaFuncAttributeMaxDynamicSharedMemorySize, ATT_SMEM);
        attr_set = true;
    }

    cvt_xh<<<256, 256>>>(x);
    cvt_wT<<<dim3(32, 32, 4), dim3(32, 8)>>>(wq, wk, wv, wo);
    qkv_mma<<<dim3(DD / 128, MT / 128, 3), 128, GEMM_SMEM>>>(cosT, sinT);
    attn_mma<<<dim3(SS / 128, HH, BB), 128, ATT_SMEM>>>();
    proj_mma<<<dim3(DD / 128, MT / 128, 1), 128, GEMM_SMEM>>>(out);
}

// round 15
// speedup vs baseline: 2.0215x; 1.0060x over previous
#include <cuda_runtime.h>
#include <cuda_fp16.h>
#include <cstdint>

// ---------------------------------------------------------------------------
// MultiHeadAttention B=2,S=2048,D=1024,H=16,Dh=64 fp32 — R15:
//  R14 + FA2 register-reuse: QK C-fragments repacked directly into PV
//  A-fragments (no P smem round-trip, no __syncwarp, Ps freed).
// ---------------------------------------------------------------------------

constexpr int BB = 2;
constexpr int SS = 2048;
constexpr int DD = 1024;
constexpr int HH = 16;
constexpr int DH = 64;
constexpr int MT = BB * SS;   // 4096

__device__ __half g_q[BB * HH * SS * DH];
__device__ __half g_k[BB * HH * SS * DH];
__device__ __half g_vt[BB * HH * DH * SS];   // V^T: [b,h,dh,s]
__device__ __half g_att[MT * DD];
__device__ __half g_xh[MT * DD];
__device__ __half g_wqt[DD * DD];            // weights transposed [n][k]
__device__ __half g_wkt[DD * DD];
__device__ __half g_wvt[DD * DD];
__device__ __half g_wot[DD * DD];

__device__ __forceinline__ uint32_t h2u(__half2 h) {
    return *reinterpret_cast<uint32_t*>(&h);
}
__device__ __forceinline__ uint32_t h2exp2(uint32_t x) {
    uint32_t r;
    asm("ex2.approx.f16x2 %0, %1;" : "=r"(r) : "r"(x));
    return r;
}
__device__ __forceinline__ void mma16(float* d, const uint32_t* a,
                                      const uint32_t* b) {
    asm volatile(
        "mma.sync.aligned.m16n8k16.row.col.f32.f16.f16.f32 "
        "{%0,%1,%2,%3}, {%4,%5,%6,%7}, {%8,%9}, {%0,%1,%2,%3};"
        : "+f"(d[0]), "+f"(d[1]), "+f"(d[2]), "+f"(d[3])
        : "r"(a[0]), "r"(a[1]), "r"(a[2]), "r"(a[3]), "r"(b[0]), "r"(b[1]));
}
__device__ __forceinline__ void ldsm4(uint32_t& r0, uint32_t& r1,
                                      uint32_t& r2, uint32_t& r3,
                                      uint32_t addr) {
    asm volatile(
        "ldmatrix.sync.aligned.m8n8.x4.shared.b16 {%0,%1,%2,%3}, [%4];"
        : "=r"(r0), "=r"(r1), "=r"(r2), "=r"(r3) : "r"(addr));
}
__device__ __forceinline__ void cp16(uint32_t dst, const void* src) {
    asm volatile("cp.async.cg.shared.global [%0], [%1], 16;"
                 :: "r"(dst), "l"(src));
}
__device__ __forceinline__ void cp_commit() {
    asm volatile("cp.async.commit_group;");
}
template <int N>
__device__ __forceinline__ void cp_wait() {
    asm volatile("cp.async.wait_group %0;" :: "n"(N));
}

// ---------------------------------------------------------------------------
// K0a: x -> half.  K0b: weights -> half, transposed [n][k].
// ---------------------------------------------------------------------------
__global__ __launch_bounds__(256) void cvt_xh(const float* __restrict__ x) {
    const int n4 = (MT * DD) >> 2;
    const float4* s4 = reinterpret_cast<const float4*>(x);
    uint2* d4 = reinterpret_cast<uint2*>(g_xh);
    for (int i = blockIdx.x * 256 + threadIdx.x; i < n4; i += gridDim.x * 256) {
        float4 v = s4[i];
        uint2 o;
        o.x = h2u(__floats2half2_rn(v.x, v.y));
        o.y = h2u(__floats2half2_rn(v.z, v.w));
        d4[i] = o;
    }
}

__global__ void cvt_wT(
    const float* __restrict__ wq, const float* __restrict__ wk,
    const float* __restrict__ wv, const float* __restrict__ wo) {
    __shared__ float t[32][33];
    const int z = blockIdx.z;
    const float* src = (z == 0) ? wq : (z == 1) ? wk : (z == 2) ? wv : wo;
    __half* dst = (z == 0) ? g_wqt : (z == 1) ? g_wkt : (z == 2) ? g_wvt : g_wot;
    const int tx = threadIdx.x, ty = threadIdx.y;
    const int kb = blockIdx.y * 32, nb = blockIdx.x * 32;
#pragma unroll
    for (int i = 0; i < 4; i++) {
        int k = kb + ty + i * 8;
        t[ty + i * 8][tx] = src[(size_t)k * DD + nb + tx];
    }
    __syncthreads();
#pragma unroll
    for (int i = 0; i < 4; i++) {
        int n = nb + ty + i * 8;
        dst[(size_t)n * DD + kb + tx] = __float2half_rn(t[tx][ty + i * 8]);
    }
}

// ---------------------------------------------------------------------------
// GEMM (R11): 128x128 tile, BK=32 halves, 4 warps, 64x64/warp, 3-stage.
// ---------------------------------------------------------------------------
constexpr int STW = 40;
constexpr int OPH = 128 * STW;
constexpr int GEMM_SMEM = 3 * 2 * OPH * 2;

__device__ __forceinline__ void gemm_stage(
    uint32_t As_s, uint32_t Bs_s, int s, const __half* __restrict__ A,
    const __half* __restrict__ Bt, int brow, int bcol, int kk, int tid)
{
#pragma unroll
    for (int i = 0; i < 4; i++) {
        int idx = tid + (i << 7);
        int r = idx >> 2, c8 = (idx & 3) << 3;
        const uint32_t doff = (uint32_t)(s * OPH + r * STW + c8) * 2;
        cp16(As_s + doff, A + (size_t)(brow + r) * DD + kk + c8);
        cp16(Bs_s + doff, Bt + (size_t)(bcol + r) * DD + kk + c8);
    }
    cp_commit();
}

template <typename EpiF>
__device__ __forceinline__ void gemm_run(
    char* sm, const __half* __restrict__ A, const __half* __restrict__ Bt,
    int brow, int bcol, EpiF epi)
{
    const uint32_t As_s = (uint32_t)__cvta_generic_to_shared(sm);
    const uint32_t Bs_s = As_s + 3 * OPH * 2;

    const int tid = threadIdx.x;
    const int lane = tid & 31;
    const int warp = tid >> 5;
    const int wm = warp >> 1, wn = warp & 1;

    const int arow = wm * 64 + (lane & 7) + ((lane >> 3) & 1) * 8;
    const int acolH = (lane >> 4) * 8;
    const int brw = wn * 64 + (lane & 7) + (lane >> 4) * 8;
    const int bcolH = ((lane >> 3) & 1) * 8;
    const uint32_t a_base = As_s + (uint32_t)(arow * STW + acolH) * 2;
    const uint32_t b_base = Bs_s + (uint32_t)(brw * STW + bcolH) * 2;

    float acc[4][8][4];
#pragma unroll
    for (int mi = 0; mi < 4; mi++)
#pragma unroll
        for (int ni = 0; ni < 8; ni++)
#pragma unroll
            for (int f = 0; f < 4; f++) acc[mi][ni][f] = 0.f;

    constexpr int NCH = DD / 32;
    gemm_stage(As_s, Bs_s, 0, A, Bt, brow, bcol, 0, tid);
    gemm_stage(As_s, Bs_s, 1, A, Bt, brow, bcol, 32, tid);

    for (int i = 0; i < NCH; i++) {
        if (i + 1 < NCH) cp_wait<1>(); else cp_wait<0>();
        __syncthreads();
        if (i + 2 < NCH)
            gemm_stage(As_s, Bs_s, (i + 2) % 3, A, Bt, brow, bcol,
                       (i + 2) * 32, tid);
        const uint32_t soff = (uint32_t)((i % 3) * OPH) * 2;
#pragma unroll
        for (int ks = 0; ks < 2; ks++) {
            const uint32_t ko = soff + (uint32_t)(ks * 16) * 2;
            uint32_t a[4][4], b[8][2];
#pragma unroll
            for (int mi = 0; mi < 4; mi++)
                ldsm4(a[mi][0], a[mi][1], a[mi][2], a[mi][3],
                      a_base + ko + (uint32_t)(mi * 16 * STW) * 2);
#pragma unroll
            for (int nj = 0; nj < 4; nj++)
                ldsm4(b[2 * nj][0], b[2 * nj][1],
                      b[2 * nj + 1][0], b[2 * nj + 1][1],
                      b_base + ko + (uint32_t)(nj * 16 * STW) * 2);
#pragma unroll
            for (int mi = 0; mi < 4; mi++)
#pragma unroll
                for (int ni = 0; ni < 8; ni++)
                    mma16(acc[mi][ni], a[mi], b[ni]);
        }
    }
    epi(acc, lane, wm, wn);
}

// ---------------------------------------------------------------------------
// K1: QKV GEMM + RoPE.  mat==2 (V): smem transpose -> g_vt[b,h,dh,s].
// ---------------------------------------------------------------------------
__global__ __launch_bounds__(128, 2) void qkv_mma(
    const float* __restrict__ cosT, const float* __restrict__ sinT)
{
    extern __shared__ char sm[];
    const int mat = blockIdx.z;
    const __half* __restrict__ w =
        (mat == 0) ? g_wqt : (mat == 1) ? g_wkt : g_wvt;
    const int brow = blockIdx.y * 128;
    const int bcol = blockIdx.x * 128;

    gemm_run(sm, g_xh, w, brow, bcol,
        [&](float acc[4][8][4], int lane, int wm, int wn) {
            const int tid = threadIdx.x;
            if (mat < 2) {
                __half* __restrict__ out = (mat == 0) ? g_q : g_k;
                const int ar = wm * 64 + (lane >> 2);
                const int ac = wn * 64 + (lane & 3) * 2;
#pragma unroll
                for (int mi = 0; mi < 4; mi++) {
#pragma unroll
                    for (int hp = 0; hp < 2; hp++) {
                        const int row = brow + ar + mi * 16 + hp * 8;
                        const int bb = row >> 11;
                        const int ss = row & (SS - 1);
#pragma unroll
                        for (int ni = 0; ni < 8; ni++) {
                            const int col = bcol + ac + ni * 8;
                            const int hh = col >> 6;
                            const int dh = col & (DH - 1);
                            float c0 = acc[mi][ni][hp * 2 + 0];
                            float c1 = acc[mi][ni][hp * 2 + 1];
                            const int fi = ss * 32 + (dh >> 1);
                            const float cs = cosT[fi], sn = sinT[fi];
                            const float o0 = c0 * cs - c1 * sn;
                            const float o1 = c0 * sn + c1 * cs;
                            c0 = o0; c1 = o1;
                            if (mat == 0) { c0 *= 0.125f; c1 *= 0.125f; }
                            *reinterpret_cast<__half2*>(
                                out + ((size_t)(bb * HH + hh) * SS + ss) * DH + dh) =
                                __floats2half2_rn(c0, c1);
                        }
                    }
                }
            } else {
                __syncthreads();
                __half* T = reinterpret_cast<__half*>(sm);  // [128][136]
                const int ar = wm * 64 + (lane >> 2);
                const int ac = wn * 64 + (lane & 3) * 2;
#pragma unroll
                for (int mi = 0; mi < 4; mi++)
#pragma unroll
                    for (int hp = 0; hp < 2; hp++) {
                        const int rl = ar + mi * 16 + hp * 8;
#pragma unroll
                        for (int ni = 0; ni < 8; ni++) {
                            const int cl = ac + ni * 8;
                            T[(cl)     * 136 + rl] =
                                __float2half_rn(acc[mi][ni][hp * 2]);
                            T[(cl + 1) * 136 + rl] =
                                __float2half_rn(acc[mi][ni][hp * 2 + 1]);
                        }
                    }
                __syncthreads();
                const int bb = brow >> 11;
                const int srow = brow & (SS - 1);
#pragma unroll
                for (int i = 0; i < 16; i++) {
                    int idx = tid + (i << 7);
                    int r = idx >> 4, c8 = (idx & 15) << 3;
                    const int dhg = bcol + r;
                    const int hh = dhg >> 6, dh = dhg & 63;
                    uint4 v = *reinterpret_cast<const uint4*>(&T[r * 136 + c8]);
                    *reinterpret_cast<uint4*>(
                        g_vt + ((size_t)(bb * HH + hh) * DH + dh) * SS +
                        srow + c8) = v;
                }
            }
        });
}

// ---------------------------------------------------------------------------
// K3: output projection (half in, fp32 out)
// ---------------------------------------------------------------------------
__global__ __launch_bounds__(128, 2) void proj_mma(float* __restrict__ Cout)
{
    extern __shared__ char sm[];
    const int brow = blockIdx.y * 128;
    const int bcol = blockIdx.x * 128;

    gemm_run(sm, g_att, g_wot, brow, bcol,
        [&](float acc[4][8][4], int lane, int wm, int wn) {
            const int ar = wm * 64 + (lane >> 2);
            const int ac = wn * 64 + (lane & 3) * 2;
#pragma unroll
            for (int mi = 0; mi < 4; mi++)
#pragma unroll
                for (int hp = 0; hp < 2; hp++) {
                    const int row = brow + ar + mi * 16 + hp * 8;
#pragma unroll
                    for (int ni = 0; ni < 8; ni++) {
                        const int col = bcol + ac + ni * 8;
                        *reinterpret_cast<float2*>(
                            Cout + (size_t)row * DD + col) =
                            make_float2(acc[mi][ni][hp * 2],
                                        acc[mi][ni][hp * 2 + 1]);
                    }
                }
        });
}

// ---------------------------------------------------------------------------
// K2: flash attention — 128 q-rows/block, 4 warps (m32n64), 2 blocks/SM,
// 3-stage KV ring, FA2 register-reuse (P never touches smem).
// Vs: 80 rows (64 data + ones row 64 + zeros). l via PV ones-column.
// smem: Qs[128][72] + Ks[3][64][72] + Vs[3][80][72] = 80640 B.
// ---------------------------------------------------------------------------
constexpr int AST = 72;                     // halves
constexpr int QS_H = 128 * AST;             // 9216
constexpr int KS_H = 64 * AST;              // 4608
constexpr int VS_H = 80 * AST;              // 5760
constexpr int ATT_SMEM = (QS_H + 3 * KS_H + 3 * VS_H) * 2;  // 80640 B

__device__ __forceinline__ void attn_stage_kv(
    uint32_t Ks_s, uint32_t Vs_s, int s,
    const __half* __restrict__ K, const __half* __restrict__ Vt,
    int kt, int tid)
{
#pragma unroll
    for (int i = 0; i < 4; i++) {
        int idx = tid + (i << 7);
        int r = idx >> 3, c8 = (idx & 7) << 3;
        cp16(Ks_s + (uint32_t)(s * KS_H + r * AST + c8) * 2,
             K + (size_t)(kt * 64 + r) * DH + c8);
        cp16(Vs_s + (uint32_t)(s * VS_H + r * AST + c8) * 2,
             Vt + (size_t)r * SS + kt * 64 + c8);
    }
    cp_commit();
}

__global__ __launch_bounds__(128, 2) void attn_mma()
{
    extern __shared__ char smc[];
    __half* Qs = reinterpret_cast<__half*>(smc);
    __half* Ks = Qs + QS_H;
    __half* Vs = Ks + 3 * KS_H;
    const uint32_t Qs_s = (uint32_t)__cvta_generic_to_shared(Qs);
    const uint32_t Ks_s = (uint32_t)__cvta_generic_to_shared(Ks);
    const uint32_t Vs_s = (uint32_t)__cvta_generic_to_shared(Vs);

    const int qt = blockIdx.x, h = blockIdx.y, b = blockIdx.z;
    const __half* __restrict__ Q  = g_q  + ((size_t)(b * HH + h) * SS + qt * 128) * DH;
    const __half* __restrict__ K  = g_k  + (size_t)(b * HH + h) * SS * DH;
    const __half* __restrict__ Vt = g_vt + (size_t)(b * HH + h) * DH * SS;

    const int tid = threadIdx.x;
    const int lane = tid & 31;
    const int warp = tid >> 5;     // 0..3
    const int qbase = warp * 32;

    // ones/zeros rows of Vs (rows 64..79, all 3 slots) — disjoint from
    // cp.async target rows 0..63.
    for (int idx = tid; idx < 3 * 16 * AST; idx += 128) {
        const int s = idx / (16 * AST);
        const int rem = idx % (16 * AST);
        const int r = 64 + rem / AST;
        const int c = rem % AST;
        Vs[s * VS_H + r * AST + c] =
            (r == 64) ? __float2half(1.f) : __float2half(0.f);
    }

    // prologue: Q + KV0 committed together (g0), then KV1 (g1)
#pragma unroll
    for (int i = 0; i < 8; i++) {
        int idx = tid + (i << 7);
        int r = idx >> 3, c8 = (idx & 7) << 3;
        cp16(Qs_s + (uint32_t)(r * AST + c8) * 2, Q + (size_t)r * DH + c8);
    }
    attn_stage_kv(Ks_s, Vs_s, 0, K, Vt, 0, tid);
    attn_stage_kv(Ks_s, Vs_s, 1, K, Vt, 1, tid);

    // ldmatrix lane bases (bytes)
    const int arow = (lane & 7) + ((lane >> 3) & 1) * 8;
    const int acolH = (lane >> 4) * 8;
    const int brw = (lane & 7) + (lane >> 4) * 8;
    const int bcolH = ((lane >> 3) & 1) * 8;
    const uint32_t qa = Qs_s + (uint32_t)((qbase + arow) * AST + acolH) * 2;
    const uint32_t kb = Ks_s + (uint32_t)(brw * AST + bcolH) * 2;
    const uint32_t vb = Vs_s + (uint32_t)(brw * AST + bcolH) * 2;

    constexpr float L2E = 1.4426950408889634f;

    float mrow[2][2];
    float o[2][9][4];   // ni=8 is the row-sum (l) column
#pragma unroll
    for (int mi = 0; mi < 2; mi++) {
#pragma unroll
        for (int hp = 0; hp < 2; hp++) mrow[mi][hp] = -1e30f;
#pragma unroll
        for (int ni = 0; ni < 9; ni++)
#pragma unroll
            for (int f = 0; f < 4; f++) o[mi][ni][f] = 0.f;
    }

    constexpr int NKT = SS / 64;  // 32

    for (int kt = 0; kt < NKT; kt++) {
        if (kt + 1 < NKT) cp_wait<1>(); else cp_wait<0>();
        __syncthreads();
        if (kt + 2 < NKT)
            attn_stage_kv(Ks_s, Vs_s, (kt + 2) % 3, K, Vt, kt + 2, tid);

        const int s = kt % 3;
        const uint32_t kOff = (uint32_t)(s * KS_H) * 2;
        const uint32_t vOff = (uint32_t)(s * VS_H) * 2;

        // ---- S = Q @ K^T ----
        float sacc[2][8][4];
#pragma unroll
        for (int mi = 0; mi < 2; mi++)
#pragma unroll
            for (int ni = 0; ni < 8; ni++)
#pragma unroll
                for (int f = 0; f < 4; f++) sacc[mi][ni][f] = 0.f;

#pragma unroll
        for (int ks = 0; ks < 4; ks++) {
            const uint32_t ko = (uint32_t)(ks * 16) * 2;
            uint32_t a[2][4], bf[8][2];
#pragma unroll
            for (int mi = 0; mi < 2; mi++)
                ldsm4(a[mi][0], a[mi][1], a[mi][2], a[mi][3],
                      qa + ko + (uint32_t)(mi * 16 * AST) * 2);
#pragma unroll
            for (int nj = 0; nj < 4; nj++)
                ldsm4(bf[2 * nj][0], bf[2 * nj][1],
                      bf[2 * nj + 1][0], bf[2 * nj + 1][1],
                      kb + kOff + ko + (uint32_t)(nj * 16 * AST) * 2);
#pragma unroll
            for (int mi = 0; mi < 2; mi++)
#pragma unroll
                for (int ni = 0; ni < 8; ni++)
                    mma16(sacc[mi][ni], a[mi], bf[ni]);
        }

        // ---- softmax in registers: pk[mi][ni][0]=exp rows r, [1]=rows r+8 ----
        uint32_t pk[2][8][2];
#pragma unroll
        for (int mi = 0; mi < 2; mi++) {
            float mL2[2];
#pragma unroll
            for (int hp = 0; hp < 2; hp++) {
                float mx = -1e30f;
#pragma unroll
                for (int ni = 0; ni < 8; ni++)
                    mx = fmaxf(mx, fmaxf(sacc[mi][ni][hp * 2],
                                         sacc[mi][ni][hp * 2 + 1]));
                mx = fmaxf(mx, __shfl_xor_sync(0xffffffffu, mx, 1));
                mx = fmaxf(mx, __shfl_xor_sync(0xffffffffu, mx, 2));
                const float mnew = fmaxf(mrow[mi][hp], mx);
                const float corr = __expf(mrow[mi][hp] - mnew);
                mrow[mi][hp] = mnew;
                mL2[hp] = mnew * L2E;
#pragma unroll
                for (int ni = 0; ni < 9; ni++) {
                    o[mi][ni][hp * 2]     *= corr;
                    o[mi][ni][hp * 2 + 1] *= corr;
                }
            }
#pragma unroll
            for (int ni = 0; ni < 8; ni++) {
                const float b0 = fmaf(sacc[mi][ni][0], L2E, -mL2[0]);
                const float b1 = fmaf(sacc[mi][ni][1], L2E, -mL2[0]);
                const float b2 = fmaf(sacc[mi][ni][2], L2E, -mL2[1]);
                const float b3 = fmaf(sacc[mi][ni][3], L2E, -mL2[1]);
                pk[mi][ni][0] = h2exp2(h2u(__floats2half2_rn(b0, b1)));
                pk[mi][ni][1] = h2exp2(h2u(__floats2half2_rn(b2, b3)));
            }
        }

        // ---- O += P @ [V^T ; ones]  (A fragments direct from pk) ----
#pragma unroll
        for (int ks = 0; ks < 4; ks++) {
            const uint32_t ko = (uint32_t)(ks * 16) * 2;
            uint32_t bf[10][2];
#pragma unroll
            for (int nj = 0; nj < 5; nj++)
                ldsm4(bf[2 * nj][0], bf[2 * nj][1],
                      bf[2 * nj + 1][0], bf[2 * nj + 1][1],
                      vb + vOff + ko + (uint32_t)(nj * 16 * AST) * 2);
#pragma unroll
            for (int mi = 0; mi < 2; mi++) {
                uint32_t a[4];
                a[0] = pk[mi][2 * ks][0];
                a[1] = pk[mi][2 * ks][1];
                a[2] = pk[mi][2 * ks + 1][0];
                a[3] = pk[mi][2 * ks + 1][1];
#pragma unroll
                for (int ni = 0; ni < 9; ni++)
                    mma16(o[mi][ni], a, bf[ni]);
            }
        }
    }

    // epilogue: l from ones-column (quad lane 0), normalize, write half
#pragma unroll
    for (int mi = 0; mi < 2; mi++)
#pragma unroll
        for (int hp = 0; hp < 2; hp++) {
            const float l = __shfl_sync(0xffffffffu, o[mi][8][hp * 2],
                                        lane & ~3);
            const float inv = 1.f / l;
            const int row = qt * 128 + qbase + mi * 16 + hp * 8 + (lane >> 2);
#pragma unroll
            for (int ni = 0; ni < 8; ni++) {
                const int col = h * 64 + ni * 8 + (lane & 3) * 2;
                *reinterpret_cast<__half2*>(
                    g_att + (size_t)(b * SS + row) * DD + col) =
                    __floats2half2_rn(o[mi][ni][hp * 2] * inv,
                                      o[mi][ni][hp * 2 + 1] * inv);
            }
        }
}

// ---------------------------------------------------------------------------
extern "C" void kernel_launch(void* const* d_in, const int* in_sizes, int n_in,
                              void* d_out, int out_size)
{
    const float* x    = (const float*)d_in[0];
    const float* cosT = (const float*)d_in[1];
    const float* sinT = (const float*)d_in[2];
    const float* wq   = (const float*)d_in[3];
    const float* wk   = (const float*)d_in[4];
    const float* wv   = (const float*)d_in[5];
    const float* wo   = (const float*)d_in[6];
    float* out = (float*)d_out;

    static bool attr_set = false;
    if (!attr_set) {
        cudaFuncSetAttribute(qkv_mma,
                             cudaFuncAttributeMaxDynamicSharedMemorySize, GEMM_SMEM);
        cudaFuncSetAttribute(proj_mma,
                             cudaFuncAttributeMaxDynamicSharedMemorySize, GEMM_SMEM);
        cudaFuncSetAttribute(attn_mma,
                             cudaFuncAttributeMaxDynamicSharedMemorySize, ATT_SMEM);
        attr_set = true;
    }

    cvt_xh<<<256, 256>>>(x);
    cvt_wT<<<dim3(32, 32, 4), dim3(32, 8)>>>(wq, wk, wv, wo);
    qkv_mma<<<dim3(DD / 128, MT / 128, 3), 128, GEMM_SMEM>>>(cosT, sinT);
    attn_mma<<<dim3(SS / 128, HH, BB), 128, ATT_SMEM>>>();
    proj_mma<<<dim3(DD / 128, MT / 128, 1), 128, GEMM_SMEM>>>(out);
}

// round 17
// speedup vs baseline: 2.0329x; 1.0057x over previous
#include <cuda_runtime.h>
#include <cuda_fp16.h>
#include <cstdint>

// ---------------------------------------------------------------------------
// MultiHeadAttention B=2,S=2048,D=1024,H=16,Dh=64 fp32 — R17:
//  R16 with the GEMM ks=1 fragment offset fixed (32 bytes, not 64):
//   * attention: V-fragments prefetched behind softmax, double-buffered per ks
//   * GEMMs: ks=0/1 fragment double-buffering inside each K chunk
// ---------------------------------------------------------------------------

constexpr int BB = 2;
constexpr int SS = 2048;
constexpr int DD = 1024;
constexpr int HH = 16;
constexpr int DH = 64;
constexpr int MT = BB * SS;   // 4096

__device__ __half g_q[BB * HH * SS * DH];
__device__ __half g_k[BB * HH * SS * DH];
__device__ __half g_vt[BB * HH * DH * SS];   // V^T: [b,h,dh,s]
__device__ __half g_att[MT * DD];
__device__ __half g_xh[MT * DD];
__device__ __half g_wqt[DD * DD];            // weights transposed [n][k]
__device__ __half g_wkt[DD * DD];
__device__ __half g_wvt[DD * DD];
__device__ __half g_wot[DD * DD];

__device__ __forceinline__ uint32_t h2u(__half2 h) {
    return *reinterpret_cast<uint32_t*>(&h);
}
__device__ __forceinline__ uint32_t h2exp2(uint32_t x) {
    uint32_t r;
    asm("ex2.approx.f16x2 %0, %1;" : "=r"(r) : "r"(x));
    return r;
}
__device__ __forceinline__ void mma16(float* d, const uint32_t* a,
                                      const uint32_t* b) {
    asm volatile(
        "mma.sync.aligned.m16n8k16.row.col.f32.f16.f16.f32 "
        "{%0,%1,%2,%3}, {%4,%5,%6,%7}, {%8,%9}, {%0,%1,%2,%3};"
        : "+f"(d[0]), "+f"(d[1]), "+f"(d[2]), "+f"(d[3])
        : "r"(a[0]), "r"(a[1]), "r"(a[2]), "r"(a[3]), "r"(b[0]), "r"(b[1]));
}
__device__ __forceinline__ void ldsm4(uint32_t& r0, uint32_t& r1,
                                      uint32_t& r2, uint32_t& r3,
                                      uint32_t addr) {
    asm volatile(
        "ldmatrix.sync.aligned.m8n8.x4.shared.b16 {%0,%1,%2,%3}, [%4];"
        : "=r"(r0), "=r"(r1), "=r"(r2), "=r"(r3) : "r"(addr));
}
__device__ __forceinline__ void cp16(uint32_t dst, const void* src) {
    asm volatile("cp.async.cg.shared.global [%0], [%1], 16;"
                 :: "r"(dst), "l"(src));
}
__device__ __forceinline__ void cp_commit() {
    asm volatile("cp.async.commit_group;");
}
template <int N>
__device__ __forceinline__ void cp_wait() {
    asm volatile("cp.async.wait_group %0;" :: "n"(N));
}

// ---------------------------------------------------------------------------
// K0a: x -> half.  K0b: weights -> half, transposed [n][k].
// ---------------------------------------------------------------------------
__global__ __launch_bounds__(256) void cvt_xh(const float* __restrict__ x) {
    const int n4 = (MT * DD) >> 2;
    const float4* s4 = reinterpret_cast<const float4*>(x);
    uint2* d4 = reinterpret_cast<uint2*>(g_xh);
    for (int i = blockIdx.x * 256 + threadIdx.x; i < n4; i += gridDim.x * 256) {
        float4 v = s4[i];
        uint2 o;
        o.x = h2u(__floats2half2_rn(v.x, v.y));
        o.y = h2u(__floats2half2_rn(v.z, v.w));
        d4[i] = o;
    }
}

__global__ void cvt_wT(
    const float* __restrict__ wq, const float* __restrict__ wk,
    const float* __restrict__ wv, const float* __restrict__ wo) {
    __shared__ float t[32][33];
    const int z = blockIdx.z;
    const float* src = (z == 0) ? wq : (z == 1) ? wk : (z == 2) ? wv : wo;
    __half* dst = (z == 0) ? g_wqt : (z == 1) ? g_wkt : (z == 2) ? g_wvt : g_wot;
    const int tx = threadIdx.x, ty = threadIdx.y;
    const int kb = blockIdx.y * 32, nb = blockIdx.x * 32;
#pragma unroll
    for (int i = 0; i < 4; i++) {
        int k = kb + ty + i * 8;
        t[ty + i * 8][tx] = src[(size_t)k * DD + nb + tx];
    }
    __syncthreads();
#pragma unroll
    for (int i = 0; i < 4; i++) {
        int n = nb + ty + i * 8;
        dst[(size_t)n * DD + kb + tx] = __float2half_rn(t[tx][ty + i * 8]);
    }
}

// ---------------------------------------------------------------------------
// GEMM: 128x128 tile, BK=32 halves, 4 warps, 64x64/warp, 3-stage,
// ks-level fragment double-buffering.
// ---------------------------------------------------------------------------
constexpr int STW = 40;
constexpr int OPH = 128 * STW;
constexpr int GEMM_SMEM = 3 * 2 * OPH * 2;

__device__ __forceinline__ void gemm_stage(
    uint32_t As_s, uint32_t Bs_s, int s, const __half* __restrict__ A,
    const __half* __restrict__ Bt, int brow, int bcol, int kk, int tid)
{
#pragma unroll
    for (int i = 0; i < 4; i++) {
        int idx = tid + (i << 7);
        int r = idx >> 2, c8 = (idx & 3) << 3;
        const uint32_t doff = (uint32_t)(s * OPH + r * STW + c8) * 2;
        cp16(As_s + doff, A + (size_t)(brow + r) * DD + kk + c8);
        cp16(Bs_s + doff, Bt + (size_t)(bcol + r) * DD + kk + c8);
    }
    cp_commit();
}

__device__ __forceinline__ void gemm_load_frags(
    uint32_t a_base, uint32_t b_base, uint32_t ko,
    uint32_t a[4][4], uint32_t b[8][2])
{
#pragma unroll
    for (int mi = 0; mi < 4; mi++)
        ldsm4(a[mi][0], a[mi][1], a[mi][2], a[mi][3],
              a_base + ko + (uint32_t)(mi * 16 * STW) * 2);
#pragma unroll
    for (int nj = 0; nj < 4; nj++)
        ldsm4(b[2 * nj][0], b[2 * nj][1],
              b[2 * nj + 1][0], b[2 * nj + 1][1],
              b_base + ko + (uint32_t)(nj * 16 * STW) * 2);
}

template <typename EpiF>
__device__ __forceinline__ void gemm_run(
    char* sm, const __half* __restrict__ A, const __half* __restrict__ Bt,
    int brow, int bcol, EpiF epi)
{
    const uint32_t As_s = (uint32_t)__cvta_generic_to_shared(sm);
    const uint32_t Bs_s = As_s + 3 * OPH * 2;

    const int tid = threadIdx.x;
    const int lane = tid & 31;
    const int warp = tid >> 5;
    const int wm = warp >> 1, wn = warp & 1;

    const int arow = wm * 64 + (lane & 7) + ((lane >> 3) & 1) * 8;
    const int acolH = (lane >> 4) * 8;
    const int brw = wn * 64 + (lane & 7) + (lane >> 4) * 8;
    const int bcolH = ((lane >> 3) & 1) * 8;
    const uint32_t a_base = As_s + (uint32_t)(arow * STW + acolH) * 2;
    const uint32_t b_base = Bs_s + (uint32_t)(brw * STW + bcolH) * 2;

    float acc[4][8][4];
#pragma unroll
    for (int mi = 0; mi < 4; mi++)
#pragma unroll
        for (int ni = 0; ni < 8; ni++)
#pragma unroll
            for (int f = 0; f < 4; f++) acc[mi][ni][f] = 0.f;

    constexpr int NCH = DD / 32;
    gemm_stage(As_s, Bs_s, 0, A, Bt, brow, bcol, 0, tid);
    gemm_stage(As_s, Bs_s, 1, A, Bt, brow, bcol, 32, tid);

    for (int i = 0; i < NCH; i++) {
        if (i + 1 < NCH) cp_wait<1>(); else cp_wait<0>();
        __syncthreads();
        if (i + 2 < NCH)
            gemm_stage(As_s, Bs_s, (i + 2) % 3, A, Bt, brow, bcol,
                       (i + 2) * 32, tid);
        const uint32_t soff = (uint32_t)((i % 3) * OPH) * 2;

        uint32_t a[2][4][4], b[2][8][2];
        gemm_load_frags(a_base, b_base, soff, a[0], b[0]);          // ks=0
        gemm_load_frags(a_base, b_base, soff + 16 * 2, a[1], b[1]); // ks=1 (+32B)
#pragma unroll
        for (int ks = 0; ks < 2; ks++)
#pragma unroll
            for (int mi = 0; mi < 4; mi++)
#pragma unroll
                for (int ni = 0; ni < 8; ni++)
                    mma16(acc[mi][ni], a[ks][mi], b[ks][ni]);
    }
    epi(acc, lane, wm, wn);
}

// ---------------------------------------------------------------------------
// K1: QKV GEMM + RoPE.  mat==2 (V): smem transpose -> g_vt[b,h,dh,s].
// ---------------------------------------------------------------------------
__global__ __launch_bounds__(128, 2) void qkv_mma(
    const float* __restrict__ cosT, const float* __restrict__ sinT)
{
    extern __shared__ char sm[];
    const int mat = blockIdx.z;
    const __half* __restrict__ w =
        (mat == 0) ? g_wqt : (mat == 1) ? g_wkt : g_wvt;
    const int brow = blockIdx.y * 128;
    const int bcol = blockIdx.x * 128;

    gemm_run(sm, g_xh, w, brow, bcol,
        [&](float acc[4][8][4], int lane, int wm, int wn) {
            const int tid = threadIdx.x;
            if (mat < 2) {
                __half* __restrict__ out = (mat == 0) ? g_q : g_k;
                const int ar = wm * 64 + (lane >> 2);
                const int ac = wn * 64 + (lane & 3) * 2;
#pragma unroll
                for (int mi = 0; mi < 4; mi++) {
#pragma unroll
                    for (int hp = 0; hp < 2; hp++) {
                        const int row = brow + ar + mi * 16 + hp * 8;
                        const int bb = row >> 11;
                        const int ss = row & (SS - 1);
#pragma unroll
                        for (int ni = 0; ni < 8; ni++) {
                            const int col = bcol + ac + ni * 8;
                            const int hh = col >> 6;
                            const int dh = col & (DH - 1);
                            float c0 = acc[mi][ni][hp * 2 + 0];
                            float c1 = acc[mi][ni][hp * 2 + 1];
                            const int fi = ss * 32 + (dh >> 1);
                            const float cs = cosT[fi], sn = sinT[fi];
                            const float o0 = c0 * cs - c1 * sn;
                            const float o1 = c0 * sn + c1 * cs;
                            c0 = o0; c1 = o1;
                            if (mat == 0) { c0 *= 0.125f; c1 *= 0.125f; }
                            *reinterpret_cast<__half2*>(
                                out + ((size_t)(bb * HH + hh) * SS + ss) * DH + dh) =
                                __floats2half2_rn(c0, c1);
                        }
                    }
                }
            } else {
                __syncthreads();
                __half* T = reinterpret_cast<__half*>(sm);  // [128][136]
                const int ar = wm * 64 + (lane >> 2);
                const int ac = wn * 64 + (lane & 3) * 2;
#pragma unroll
                for (int mi = 0; mi < 4; mi++)
#pragma unroll
                    for (int hp = 0; hp < 2; hp++) {
                        const int rl = ar + mi * 16 + hp * 8;
#pragma unroll
                        for (int ni = 0; ni < 8; ni++) {
                            const int cl = ac + ni * 8;
                            T[(cl)     * 136 + rl] =
                                __float2half_rn(acc[mi][ni][hp * 2]);
                            T[(cl + 1) * 136 + rl] =
                                __float2half_rn(acc[mi][ni][hp * 2 + 1]);
                        }
                    }
                __syncthreads();
                const int bb = brow >> 11;
                const int srow = brow & (SS - 1);
#pragma unroll
                for (int i = 0; i < 16; i++) {
                    int idx = tid + (i << 7);
                    int r = idx >> 4, c8 = (idx & 15) << 3;
                    const int dhg = bcol + r;
                    const int hh = dhg >> 6, dh = dhg & 63;
                    uint4 v = *reinterpret_cast<const uint4*>(&T[r * 136 + c8]);
                    *reinterpret_cast<uint4*>(
                        g_vt + ((size_t)(bb * HH + hh) * DH + dh) * SS +
                        srow + c8) = v;
                }
            }
        });
}

// ---------------------------------------------------------------------------
// K3: output projection (half in, fp32 out)
// ---------------------------------------------------------------------------
__global__ __launch_bounds__(128, 2) void proj_mma(float* __restrict__ Cout)
{
    extern __shared__ char sm[];
    const int brow = blockIdx.y * 128;
    const int bcol = blockIdx.x * 128;

    gemm_run(sm, g_att, g_wot, brow, bcol,
        [&](float acc[4][8][4], int lane, int wm, int wn) {
            const int ar = wm * 64 + (lane >> 2);
            const int ac = wn * 64 + (lane & 3) * 2;
#pragma unroll
            for (int mi = 0; mi < 4; mi++)
#pragma unroll
                for (int hp = 0; hp < 2; hp++) {
                    const int row = brow + ar + mi * 16 + hp * 8;
#pragma unroll
                    for (int ni = 0; ni < 8; ni++) {
                        const int col = bcol + ac + ni * 8;
                        *reinterpret_cast<float2*>(
                            Cout + (size_t)row * DD + col) =
                            make_float2(acc[mi][ni][hp * 2],
                                        acc[mi][ni][hp * 2 + 1]);
                    }
                }
        });
}

// ---------------------------------------------------------------------------
// K2: flash attention — 128 q-rows/block, 4 warps (m32n64), 2 blocks/SM,
// 3-stage KV ring, FA2 register P, V-fragments prefetched behind softmax
// and double-buffered across ks.
// smem: Qs[128][72] + Ks[3][64][72] + Vs[3][80][72] = 80640 B.
// ---------------------------------------------------------------------------
constexpr int AST = 72;
constexpr int QS_H = 128 * AST;
constexpr int KS_H = 64 * AST;
constexpr int VS_H = 80 * AST;
constexpr int ATT_SMEM = (QS_H + 3 * KS_H + 3 * VS_H) * 2;  // 80640 B

__device__ __forceinline__ void attn_stage_kv(
    uint32_t Ks_s, uint32_t Vs_s, int s,
    const __half* __restrict__ K, const __half* __restrict__ Vt,
    int kt, int tid)
{
#pragma unroll
    for (int i = 0; i < 4; i++) {
        int idx = tid + (i << 7);
        int r = idx >> 3, c8 = (idx & 7) << 3;
        cp16(Ks_s + (uint32_t)(s * KS_H + r * AST + c8) * 2,
             K + (size_t)(kt * 64 + r) * DH + c8);
        cp16(Vs_s + (uint32_t)(s * VS_H + r * AST + c8) * 2,
             Vt + (size_t)r * SS + kt * 64 + c8);
    }
    cp_commit();
}

__device__ __forceinline__ void attn_load_v(
    uint32_t vb, uint32_t vOff, int ks, uint32_t bf[10][2])
{
    const uint32_t ko = vOff + (uint32_t)(ks * 16) * 2;
#pragma unroll
    for (int nj = 0; nj < 5; nj++)
        ldsm4(bf[2 * nj][0], bf[2 * nj][1],
              bf[2 * nj + 1][0], bf[2 * nj + 1][1],
              vb + ko + (uint32_t)(nj * 16 * AST) * 2);
}

__global__ __launch_bounds__(128, 2) void attn_mma()
{
    extern __shared__ char smc[];
    __half* Qs = reinterpret_cast<__half*>(smc);
    __half* Ks = Qs + QS_H;
    __half* Vs = Ks + 3 * KS_H;
    const uint32_t Qs_s = (uint32_t)__cvta_generic_to_shared(Qs);
    const uint32_t Ks_s = (uint32_t)__cvta_generic_to_shared(Ks);
    const uint32_t Vs_s = (uint32_t)__cvta_generic_to_shared(Vs);

    const int qt = blockIdx.x, h = blockIdx.y, b = blockIdx.z;
    const __half* __restrict__ Q  = g_q  + ((size_t)(b * HH + h) * SS + qt * 128) * DH;
    const __half* __restrict__ K  = g_k  + (size_t)(b * HH + h) * SS * DH;
    const __half* __restrict__ Vt = g_vt + (size_t)(b * HH + h) * DH * SS;

    const int tid = threadIdx.x;
    const int lane = tid & 31;
    const int warp = tid >> 5;
    const int qbase = warp * 32;

    // ones/zeros rows of Vs (rows 64..79, all 3 slots)
    for (int idx = tid; idx < 3 * 16 * AST; idx += 128) {
        const int s = idx / (16 * AST);
        const int rem = idx % (16 * AST);
        const int r = 64 + rem / AST;
        const int c = rem % AST;
        Vs[s * VS_H + r * AST + c] =
            (r == 64) ? __float2half(1.f) : __float2half(0.f);
    }

    // prologue: Q + KV0 (g0), KV1 (g1)
#pragma unroll
    for (int i = 0; i < 8; i++) {
        int idx = tid + (i << 7);
        int r = idx >> 3, c8 = (idx & 7) << 3;
        cp16(Qs_s + (uint32_t)(r * AST + c8) * 2, Q + (size_t)r * DH + c8);
    }
    attn_stage_kv(Ks_s, Vs_s, 0, K, Vt, 0, tid);
    attn_stage_kv(Ks_s, Vs_s, 1, K, Vt, 1, tid);

    // ldmatrix lane bases (bytes)
    const int arow = (lane & 7) + ((lane >> 3) & 1) * 8;
    const int acolH = (lane >> 4) * 8;
    const int brw = (lane & 7) + (lane >> 4) * 8;
    const int bcolH = ((lane >> 3) & 1) * 8;
    const uint32_t qa = Qs_s + (uint32_t)((qbase + arow) * AST + acolH) * 2;
    const uint32_t kb = Ks_s + (uint32_t)(brw * AST + bcolH) * 2;
    const uint32_t vb = Vs_s + (uint32_t)(brw * AST + bcolH) * 2;

    constexpr float L2E = 1.4426950408889634f;

    float mrow[2][2];
    float o[2][9][4];
#pragma unroll
    for (int mi = 0; mi < 2; mi++) {
#pragma unroll
        for (int hp = 0; hp < 2; hp++) mrow[mi][hp] = -1e30f;
#pragma unroll
        for (int ni = 0; ni < 9; ni++)
#pragma unroll
            for (int f = 0; f < 4; f++) o[mi][ni][f] = 0.f;
    }

    constexpr int NKT = SS / 64;  // 32

    for (int kt = 0; kt < NKT; kt++) {
        if (kt + 1 < NKT) cp_wait<1>(); else cp_wait<0>();
        __syncthreads();
        if (kt + 2 < NKT)
            attn_stage_kv(Ks_s, Vs_s, (kt + 2) % 3, K, Vt, kt + 2, tid);

        const int s = kt % 3;
        const uint32_t kOff = (uint32_t)(s * KS_H) * 2;
        const uint32_t vOff = (uint32_t)(s * VS_H) * 2;

        // ---- S = Q @ K^T ----
        float sacc[2][8][4];
#pragma unroll
        for (int mi = 0; mi < 2; mi++)
#pragma unroll
            for (int ni = 0; ni < 8; ni++)
#pragma unroll
                for (int f = 0; f < 4; f++) sacc[mi][ni][f] = 0.f;

#pragma unroll
        for (int ks = 0; ks < 4; ks++) {
            const uint32_t ko = (uint32_t)(ks * 16) * 2;
            uint32_t a[2][4], bf[8][2];
#pragma unroll
            for (int mi = 0; mi < 2; mi++)
                ldsm4(a[mi][0], a[mi][1], a[mi][2], a[mi][3],
                      qa + ko + (uint32_t)(mi * 16 * AST) * 2);
#pragma unroll
            for (int nj = 0; nj < 4; nj++)
                ldsm4(bf[2 * nj][0], bf[2 * nj][1],
                      bf[2 * nj + 1][0], bf[2 * nj + 1][1],
                      kb + kOff + ko + (uint32_t)(nj * 16 * AST) * 2);
#pragma unroll
            for (int mi = 0; mi < 2; mi++)
#pragma unroll
                for (int ni = 0; ni < 8; ni++)
                    mma16(sacc[mi][ni], a[mi], bf[ni]);
        }

        // ---- prefetch V fragments for ks=0 (hidden behind softmax) ----
        uint32_t bfv[2][10][2];
        attn_load_v(vb, vOff, 0, bfv[0]);

        // ---- softmax in registers -> pk ----
        uint32_t pk[2][8][2];
#pragma unroll
        for (int mi = 0; mi < 2; mi++) {
            float mL2[2];
#pragma unroll
            for (int hp = 0; hp < 2; hp++) {
                float mx = -1e30f;
#pragma unroll
                for (int ni = 0; ni < 8; ni++)
                    mx = fmaxf(mx, fmaxf(sacc[mi][ni][hp * 2],
                                         sacc[mi][ni][hp * 2 + 1]));
                mx = fmaxf(mx, __shfl_xor_sync(0xffffffffu, mx, 1));
                mx = fmaxf(mx, __shfl_xor_sync(0xffffffffu, mx, 2));
                const float mnew = fmaxf(mrow[mi][hp], mx);
                const float corr = __expf(mrow[mi][hp] - mnew);
                mrow[mi][hp] = mnew;
                mL2[hp] = mnew * L2E;
#pragma unroll
                for (int ni = 0; ni < 9; ni++) {
                    o[mi][ni][hp * 2]     *= corr;
                    o[mi][ni][hp * 2 + 1] *= corr;
                }
            }
#pragma unroll
            for (int ni = 0; ni < 8; ni++) {
                const float b0 = fmaf(sacc[mi][ni][0], L2E, -mL2[0]);
                const float b1 = fmaf(sacc[mi][ni][1], L2E, -mL2[0]);
                const float b2 = fmaf(sacc[mi][ni][2], L2E, -mL2[1]);
                const float b3 = fmaf(sacc[mi][ni][3], L2E, -mL2[1]);
                pk[mi][ni][0] = h2exp2(h2u(__floats2half2_rn(b0, b1)));
                pk[mi][ni][1] = h2exp2(h2u(__floats2half2_rn(b2, b3)));
            }
        }

        // ---- O += P @ [V^T ; ones]  (V double-buffered across ks) ----
#pragma unroll
        for (int ks = 0; ks < 4; ks++) {
            const int cur = ks & 1;
            if (ks < 3) attn_load_v(vb, vOff, ks + 1, bfv[cur ^ 1]);
#pragma unroll
            for (int mi = 0; mi < 2; mi++) {
                uint32_t a[4];
                a[0] = pk[mi][2 * ks][0];
                a[1] = pk[mi][2 * ks][1];
                a[2] = pk[mi][2 * ks + 1][0];
                a[3] = pk[mi][2 * ks + 1][1];
#pragma unroll
                for (int ni = 0; ni < 9; ni++)
                    mma16(o[mi][ni], a, bfv[cur][ni]);
            }
        }
    }

    // epilogue: l from ones-column (quad lane 0), normalize, write half
#pragma unroll
    for (int mi = 0; mi < 2; mi++)
#pragma unroll
        for (int hp = 0; hp < 2; hp++) {
            const float l = __shfl_sync(0xffffffffu, o[mi][8][hp * 2],
                                        lane & ~3);
            const float inv = 1.f / l;
            const int row = qt * 128 + qbase + mi * 16 + hp * 8 + (lane >> 2);
#pragma unroll
            for (int ni = 0; ni < 8; ni++) {
                const int col = h * 64 + ni * 8 + (lane & 3) * 2;
                *reinterpret_cast<__half2*>(
                    g_att + (size_t)(b * SS + row) * DD + col) =
                    __floats2half2_rn(o[mi][ni][hp * 2] * inv,
                                      o[mi][ni][hp * 2 + 1] * inv);
            }
        }
}

// ---------------------------------------------------------------------------
extern "C" void kernel_launch(void* const* d_in, const int* in_sizes, int n_in,
                              void* d_out, int out_size)
{
    const float* x    = (const float*)d_in[0];
    const float* cosT = (const float*)d_in[1];
    const float* sinT = (const float*)d_in[2];
    const float* wq   = (const float*)d_in[3];
    const float* wk   = (const float*)d_in[4];
    const float* wv   = (const float*)d_in[5];
    const float* wo   = (const float*)d_in[6];
    float* out = (float*)d_out;

    static bool attr_set = false;
    if (!attr_set) {
        cudaFuncSetAttribute(qkv_mma,
                             cudaFuncAttributeMaxDynamicSharedMemorySize, GEMM_SMEM);
        cudaFuncSetAttribute(proj_mma,
                             cudaFuncAttributeMaxDynamicSharedMemorySize, GEMM_SMEM);
        cudaFuncSetAttribute(attn_mma,
                             cudaFuncAttributeMaxDynamicSharedMemorySize, ATT_SMEM);
        attr_set = true;
    }

    cvt_xh<<<256, 256>>>(x);
    cvt_wT<<<dim3(32, 32, 4), dim3(32, 8)>>>(wq, wk, wv, wo);
    qkv_mma<<<dim3(DD / 128, MT / 128, 3), 128, GEMM_SMEM>>>(cosT, sinT);
    attn_mma<<<dim3(SS / 128, HH, BB), 128, ATT_SMEM>>>();
    proj_mma<<<dim3(DD / 128, MT / 128, 1), 128, GEMM_SMEM>>>(out);
}